// round 10
// baseline (speedup 1.0000x reference)
#include <cuda_runtime.h>
#include <cuda_bf16.h>
#include <mma.h>
#include <cstdint>

using namespace nvcuda;

// Problem constants (fixed by the reference)
#define NTOT   2048
#define NGR    32
#define NPG    64
#define C      384
#define G12    12
#define HEFF   2
#define GH     24
#define HD     16

#define XN (NTOT * C)        // 786432
#define WN (C * C)           // 147456

// Scratch (device globals — no allocation allowed)
__device__ float g_q[XN];    // z=0 partials (+bias)
__device__ float g_k[XN];
__device__ float g_v[XN];
__device__ float g_q2[XN];   // z=1 partials
__device__ float g_k2[XN];
__device__ float g_v2[XN];
__device__ float g_o2[XN];   // O-proj z=1 partial
__device__ __nv_bfloat16 g_xh[XN];
__device__ __nv_bfloat16 g_xm[XN];
__device__ __nv_bfloat16 g_wh[4 * WN];   // Wq | Wk | Wv | Wo  (row-major [K,N])
__device__ __nv_bfloat16 g_wm[4 * WN];
__device__ __nv_bfloat16 g_ah[XN];       // attention output hi
__device__ __nv_bfloat16 g_am[XN];       // attention output mid

// ---------------------------------------------------------------------------
// cp.async helpers
// ---------------------------------------------------------------------------
__device__ __forceinline__ void cp16(unsigned int dst, const void* src) {
    asm volatile("cp.async.cg.shared.global [%0], [%1], 16;\n" :: "r"(dst), "l"(src));
}
__device__ __forceinline__ void cp_commit() {
    asm volatile("cp.async.commit_group;\n");
}
template <int N>
__device__ __forceinline__ void cp_wait() {
    asm volatile("cp.async.wait_group %0;\n" :: "n"(N));
}

// ---------------------------------------------------------------------------
// Combined split kernel:
//  blocks [0, 768):    x -> bf16 hi/mid (elementwise, 4 els/thread)
//  blocks [768, 912):  4 weight matrices -> bf16 hi/mid (elementwise tiles)
// ---------------------------------------------------------------------------
__global__ __launch_bounds__(256) void split_kernel(
    const float* __restrict__ x,
    const float* __restrict__ wq, const float* __restrict__ wk,
    const float* __restrict__ wv, const float* __restrict__ wo,
    __nv_bfloat16* __restrict__ xh, __nv_bfloat16* __restrict__ xm,
    __nv_bfloat16* __restrict__ wh, __nv_bfloat16* __restrict__ wm)
{
    const int bid = blockIdx.x;
    const float* src;
    __nv_bfloat16 *dh, *dm;
    int loc;
    if (bid < XN / 1024) {
        loc = (bid * 256 + threadIdx.x) * 4;
        src = x; dh = xh; dm = xm;
    } else {
        int w = ((bid - XN / 1024) * 256 + threadIdx.x) * 4;   // [0, 4*WN)
        int m = w / WN;
        loc = w - m * WN;
        src = (m == 0) ? wq : (m == 1) ? wk : (m == 2) ? wv : wo;
        dh = wh + m * WN; dm = wm + m * WN;
    }
    float4 v4 = *reinterpret_cast<const float4*>(&src[loc]);
    float v[4] = {v4.x, v4.y, v4.z, v4.w};
    __nv_bfloat16 h[4], m_[4];
    #pragma unroll
    for (int e = 0; e < 4; e++) {
        h[e]  = __float2bfloat16(v[e]);
        m_[e] = __float2bfloat16(v[e] - __bfloat162float(h[e]));
    }
    __nv_bfloat162 hp0(h[0], h[1]), hp1(h[2], h[3]);
    __nv_bfloat162 mp0(m_[0], m_[1]), mp1(m_[2], m_[3]);
    *reinterpret_cast<uint2*>(&dh[loc]) = make_uint2(
        *reinterpret_cast<unsigned*>(&hp0), *reinterpret_cast<unsigned*>(&hp1));
    *reinterpret_cast<uint2*>(&dm[loc]) = make_uint2(
        *reinterpret_cast<unsigned*>(&mp0), *reinterpret_cast<unsigned*>(&mp1));
}

// ---------------------------------------------------------------------------
// Split-K pipelined wmma GEMM on pre-split bf16 (hi+mid, 3 MMA products):
//   partial_z[M,N] = A[M, z*K/2 : (z+1)*K/2] @ W[.., N]  (+bias if z==0)
// BM=64, BN=64, BK=32, 128 threads = 4 warps (each 32x32 -> 4 indep chains).
// 3-stage cp.async ring. blockIdx.x selects weight matrix (QKV fusion),
// blockIdx.z selects the K half.
// ---------------------------------------------------------------------------
#define AST 40   // A smem row stride (elems): 80B
#define BST 72   // B smem row stride (elems): 144B
#define AH_O 0
#define AM_O 5120                    // 64*80
#define BH_O 10240
#define BM_O 14848                   // +32*144
#define STG_BYTES 19456
#define DSM_BYTES (3 * STG_BYTES)    // 58368

__global__ __launch_bounds__(128) void gemm_bf16s_kernel(
    const __nv_bfloat16* __restrict__ Ah, const __nv_bfloat16* __restrict__ Am,
    const __nv_bfloat16* __restrict__ Wh, const __nv_bfloat16* __restrict__ Wm,
    const float* __restrict__ bias0, const float* __restrict__ bias1, const float* __restrict__ bias2,
    float* __restrict__ O0, float* __restrict__ O1, float* __restrict__ O2,
    float* __restrict__ P0, float* __restrict__ P1, float* __restrict__ P2,
    int K, int N)
{
    const int ntiles = N >> 6;
    const int which = blockIdx.x / ntiles;
    const int bc    = blockIdx.x % ntiles;
    const int br    = blockIdx.y;
    const int z     = blockIdx.z;

    const __nv_bfloat16* Bh = Wh + (long)which * K * N;
    const __nv_bfloat16* Bm = Wm + (long)which * K * N;
    const float* bias = (which == 0) ? bias0 : (which == 1) ? bias1 : bias2;
    float* O = (z == 0) ? ((which == 0) ? O0 : (which == 1) ? O1 : O2)
                        : ((which == 0) ? P0 : (which == 1) ? P1 : P2);

    extern __shared__ __align__(16) unsigned char dsm[];
    const unsigned int sbase = (unsigned int)__cvta_generic_to_shared(dsm);

    const int tid  = threadIdx.x;
    const int warp = tid >> 5;
    const int wr   = warp >> 1;       // 0..1: 32-row band
    const int wc   = warp & 1;        // 0..1: 32-col band

    const int halfK = K >> 1;
    const int kbeg  = z * halfK;
    const int niter = halfK >> 5;      // 6 for K=384

    // Per-thread load coords. A: 2 segs of 16B; r=idx>>2, c=idx&3.
    const int a_r0 = tid >> 2,          a_c0 = (tid & 3) * 16;
    const int a_r1 = (tid + 128) >> 2,  a_c1 = ((tid + 128) & 3) * 16;
    // B: 2 segs; r=idx>>3, c=idx&7.
    const int b_r0 = tid >> 3,          b_c0 = (tid & 7) * 16;
    const int b_r1 = (tid + 128) >> 3,  b_c1 = ((tid + 128) & 7) * 16;

    const __nv_bfloat16* agh0 = Ah + (long)(br * 64 + a_r0) * K + kbeg + (a_c0 >> 1);
    const __nv_bfloat16* agh1 = Ah + (long)(br * 64 + a_r1) * K + kbeg + (a_c1 >> 1);
    const __nv_bfloat16* agm0 = Am + (long)(br * 64 + a_r0) * K + kbeg + (a_c0 >> 1);
    const __nv_bfloat16* agm1 = Am + (long)(br * 64 + a_r1) * K + kbeg + (a_c1 >> 1);
    const __nv_bfloat16* bgh0 = Bh + (long)(kbeg + b_r0) * N + bc * 64 + (b_c0 >> 1);
    const __nv_bfloat16* bgh1 = Bh + (long)(kbeg + b_r1) * N + bc * 64 + (b_c1 >> 1);
    const __nv_bfloat16* bgm0 = Bm + (long)(kbeg + b_r0) * N + bc * 64 + (b_c0 >> 1);
    const __nv_bfloat16* bgm1 = Bm + (long)(kbeg + b_r1) * N + bc * 64 + (b_c1 >> 1);

    const unsigned int adh0 = sbase + AH_O + a_r0 * (AST * 2) + a_c0;
    const unsigned int adh1 = sbase + AH_O + a_r1 * (AST * 2) + a_c1;
    const unsigned int adm0 = sbase + AM_O + a_r0 * (AST * 2) + a_c0;
    const unsigned int adm1 = sbase + AM_O + a_r1 * (AST * 2) + a_c1;
    const unsigned int bdh0 = sbase + BH_O + b_r0 * (BST * 2) + b_c0;
    const unsigned int bdh1 = sbase + BH_O + b_r1 * (BST * 2) + b_c1;
    const unsigned int bdm0 = sbase + BM_O + b_r0 * (BST * 2) + b_c0;
    const unsigned int bdm1 = sbase + BM_O + b_r1 * (BST * 2) + b_c1;

    // Chunk loader (stage = s, K offset = ch*32 within this half)
    auto load_chunk = [&](int s, int ch) {
        const unsigned sb = s * STG_BYTES;
        const int ko = ch * 32;
        cp16(adh0 + sb, agh0 + ko);
        cp16(adh1 + sb, agh1 + ko);
        cp16(adm0 + sb, agm0 + ko);
        cp16(adm1 + sb, agm1 + ko);
        cp16(bdh0 + sb, bgh0 + (long)ko * N);
        cp16(bdh1 + sb, bgh1 + (long)ko * N);
        cp16(bdm0 + sb, bgm0 + (long)ko * N);
        cp16(bdm1 + sb, bgm1 + (long)ko * N);
        cp_commit();
    };

    // Prefetch chunks 0, 1
    load_chunk(0, 0);
    load_chunk(1, 1);

    wmma::fragment<wmma::accumulator, 16, 16, 16, float> acc[2][2];
    #pragma unroll
    for (int i = 0; i < 2; i++)
        #pragma unroll
        for (int j = 0; j < 2; j++)
            wmma::fill_fragment(acc[i][j], 0.0f);

    int s = 0;
    for (int it = 0; it < niter; it++) {
        if (it + 2 < niter) {
            load_chunk((s + 2) % 3, it + 2);
            cp_wait<2>();
        } else if (it + 1 < niter) {
            cp_wait<1>();
        } else {
            cp_wait<0>();
        }
        __syncthreads();

        const __nv_bfloat16* ash = reinterpret_cast<const __nv_bfloat16*>(dsm + s * STG_BYTES + AH_O);
        const __nv_bfloat16* asm_ = reinterpret_cast<const __nv_bfloat16*>(dsm + s * STG_BYTES + AM_O);
        const __nv_bfloat16* bsh = reinterpret_cast<const __nv_bfloat16*>(dsm + s * STG_BYTES + BH_O);
        const __nv_bfloat16* bsm = reinterpret_cast<const __nv_bfloat16*>(dsm + s * STG_BYTES + BM_O);

        #pragma unroll
        for (int ks = 0; ks < 2; ks++) {
            wmma::fragment<wmma::matrix_a, 16, 16, 16, __nv_bfloat16, wmma::row_major> ah[2], am[2];
            wmma::fragment<wmma::matrix_b, 16, 16, 16, __nv_bfloat16, wmma::row_major> bh[2], bm[2];
            #pragma unroll
            for (int i = 0; i < 2; i++) {
                wmma::load_matrix_sync(ah[i], ash + (wr * 32 + i * 16) * AST + ks * 16, AST);
                wmma::load_matrix_sync(am[i], asm_ + (wr * 32 + i * 16) * AST + ks * 16, AST);
            }
            #pragma unroll
            for (int j = 0; j < 2; j++) {
                wmma::load_matrix_sync(bh[j], bsh + (ks * 16) * BST + wc * 32 + j * 16, BST);
                wmma::load_matrix_sync(bm[j], bsm + (ks * 16) * BST + wc * 32 + j * 16, BST);
            }
            #pragma unroll
            for (int i = 0; i < 2; i++)
                #pragma unroll
                for (int j = 0; j < 2; j++)
                    wmma::mma_sync(acc[i][j], ah[i], bh[j], acc[i][j]);
            #pragma unroll
            for (int i = 0; i < 2; i++)
                #pragma unroll
                for (int j = 0; j < 2; j++)
                    wmma::mma_sync(acc[i][j], ah[i], bm[j], acc[i][j]);
            #pragma unroll
            for (int i = 0; i < 2; i++)
                #pragma unroll
                for (int j = 0; j < 2; j++)
                    wmma::mma_sync(acc[i][j], am[i], bh[j], acc[i][j]);
        }
        __syncthreads();
        s = (s + 1) % 3;
    }

    // Epilogue: accumulators -> aliased fp32 smem -> global
    float (*Cs)[64] = reinterpret_cast<float(*)[64]>(dsm);
    #pragma unroll
    for (int i = 0; i < 2; i++)
        #pragma unroll
        for (int j = 0; j < 2; j++)
            wmma::store_matrix_sync(&Cs[wr * 32 + i * 16][wc * 32 + j * 16],
                                    acc[i][j], 64, wmma::mem_row_major);
    __syncthreads();

    #pragma unroll
    for (int l = 0; l < 32; l++) {
        int idx = tid + l * 128;
        int r = idx >> 6, c = idx & 63;
        float b = (z == 0) ? bias[bc * 64 + c] : 0.0f;
        O[(long)(br * 64 + r) * N + bc * 64 + c] = Cs[r][c] + b;
    }
}

// ---------------------------------------------------------------------------
// out += partial (for the O-projection split-K reduce)
// ---------------------------------------------------------------------------
__global__ __launch_bounds__(256) void addp_kernel(float* __restrict__ out,
                                                   const float* __restrict__ p)
{
    int idx = (blockIdx.x * 256 + threadIdx.x) * 4;
    float4 a = *reinterpret_cast<float4*>(&out[idx]);
    float4 b = *reinterpret_cast<const float4*>(&p[idx]);
    a.x += b.x; a.y += b.y; a.z += b.z; a.w += b.w;
    *reinterpret_cast<float4*>(&out[idx]) = a;
}

// ---------------------------------------------------------------------------
// Dense attention per (graph, group-head), RoPE fused. Sums the two split-K
// partials of q,k,v during load (free reduce). Single-pass softmax.
// Writes bf16 hi/mid for the O-projection GEMM.
// ---------------------------------------------------------------------------
__global__ __launch_bounds__(256) void attn_kernel(const float* __restrict__ pos,
                                                   const float* __restrict__ freqs)
{
    const int sub   = threadIdx.x >> 6;
    const int i     = threadIdx.x & 63;
    const int gh    = blockIdx.x * 4 + sub;
    const int graph = blockIdx.y;
    const int h     = gh & 1;

    __shared__ float Ks[4][64][16];
    __shared__ float Vs[4][64][16];

    const int node = graph * NPG + i;
    const int off  = node * C + gh * HD;

    float qr[16], kr[16];
    {
        const float4* qa = reinterpret_cast<const float4*>(g_q + off);
        const float4* qb = reinterpret_cast<const float4*>(g_q2 + off);
        const float4* ka = reinterpret_cast<const float4*>(g_k + off);
        const float4* kb = reinterpret_cast<const float4*>(g_k2 + off);
        const float4* va = reinterpret_cast<const float4*>(g_v + off);
        const float4* vb = reinterpret_cast<const float4*>(g_v2 + off);
        float4* vs = reinterpret_cast<float4*>(&Vs[sub][i][0]);
        #pragma unroll
        for (int t = 0; t < 4; t++) {
            float4 q0 = qa[t], q1 = qb[t];
            qr[4*t+0] = q0.x + q1.x; qr[4*t+1] = q0.y + q1.y;
            qr[4*t+2] = q0.z + q1.z; qr[4*t+3] = q0.w + q1.w;
            float4 k0 = ka[t], k1 = kb[t];
            kr[4*t+0] = k0.x + k1.x; kr[4*t+1] = k0.y + k1.y;
            kr[4*t+2] = k0.z + k1.z; kr[4*t+3] = k0.w + k1.w;
            float4 v0 = va[t], v1 = vb[t];
            float4 vsum = make_float4(v0.x + v1.x, v0.y + v1.y,
                                      v0.z + v1.z, v0.w + v1.w);
            vs[t] = vsum;
        }
    }

    const float p0 = pos[node * 3 + 0];
    const float p1 = pos[node * 3 + 1];
    const float p2 = pos[node * 3 + 2];
    #pragma unroll
    for (int f = 0; f < 8; f++) {
        float th = p0 * freqs[ 0 + h * 8 + f]
                 + p1 * freqs[16 + h * 8 + f]
                 + p2 * freqs[32 + h * 8 + f];
        float s, c;
        __sincosf(th, &s, &c);
        float q1 = qr[2*f], q2 = qr[2*f+1];
        qr[2*f]   = q1 * c - q2 * s;
        qr[2*f+1] = q1 * s + q2 * c;
        float k1 = kr[2*f], k2 = kr[2*f+1];
        kr[2*f]   = k1 * c - k2 * s;
        kr[2*f+1] = k1 * s + k2 * c;
    }
    #pragma unroll
    for (int d = 0; d < 16; d++) qr[d] *= 0.25f;
    #pragma unroll
    for (int d = 0; d < 16; d++) Ks[sub][i][d] = kr[d];
    __syncthreads();

    float den = 0.f;
    float o[16] = {};
    #pragma unroll 2
    for (int j = 0; j < 64; j++) {
        float s = 0.f;
        #pragma unroll
        for (int d = 0; d < 16; d++) s = fmaf(qr[d], Ks[sub][j][d], s);
        float e = __expf(s);
        den += e;
        #pragma unroll
        for (int d = 0; d < 16; d++) o[d] = fmaf(e, Vs[sub][j][d], o[d]);
    }
    float inv = 1.f / den;

    __nv_bfloat16 hb[16], mb[16];
    #pragma unroll
    for (int d = 0; d < 16; d++) {
        float val = o[d] * inv;
        hb[d] = __float2bfloat16(val);
        mb[d] = __float2bfloat16(val - __bfloat162float(hb[d]));
    }
    uint4 uh0, uh1, um0, um1;
    unsigned* uhp0 = &uh0.x; unsigned* uhp1 = &uh1.x;
    unsigned* ump0 = &um0.x; unsigned* ump1 = &um1.x;
    #pragma unroll
    for (int t = 0; t < 4; t++) {
        __nv_bfloat162 a(hb[2*t], hb[2*t+1]);       uhp0[t] = *reinterpret_cast<unsigned*>(&a);
        __nv_bfloat162 b(hb[8+2*t], hb[8+2*t+1]);   uhp1[t] = *reinterpret_cast<unsigned*>(&b);
        __nv_bfloat162 c2(mb[2*t], mb[2*t+1]);      ump0[t] = *reinterpret_cast<unsigned*>(&c2);
        __nv_bfloat162 d2(mb[8+2*t], mb[8+2*t+1]);  ump1[t] = *reinterpret_cast<unsigned*>(&d2);
    }
    uint4* ah = reinterpret_cast<uint4*>(&g_ah[off]);
    uint4* am = reinterpret_cast<uint4*>(&g_am[off]);
    ah[0] = uh0; ah[1] = uh1;
    am[0] = um0; am[1] = um1;
}

// ---------------------------------------------------------------------------
extern "C" void kernel_launch(void* const* d_in, const int* in_sizes, int n_in,
                              void* d_out, int out_size)
{
    const float* x     = (const float*)d_in[0];
    const float* pos   = (const float*)d_in[1];
    const float* Wq    = (const float*)d_in[2];
    const float* bq    = (const float*)d_in[3];
    const float* Wk    = (const float*)d_in[4];
    const float* bk    = (const float*)d_in[5];
    const float* Wv    = (const float*)d_in[6];
    const float* bv    = (const float*)d_in[7];
    const float* Wo    = (const float*)d_in[8];
    const float* bo    = (const float*)d_in[9];
    const float* rfreq = (const float*)d_in[10];
    float* out = (float*)d_out;

    float *qp, *kp, *vp, *qp2, *kp2, *vp2, *op2;
    __nv_bfloat16 *xh, *xm, *wh, *wm, *ahp, *amp;
    cudaGetSymbolAddress((void**)&qp, g_q);
    cudaGetSymbolAddress((void**)&kp, g_k);
    cudaGetSymbolAddress((void**)&vp, g_v);
    cudaGetSymbolAddress((void**)&qp2, g_q2);
    cudaGetSymbolAddress((void**)&kp2, g_k2);
    cudaGetSymbolAddress((void**)&vp2, g_v2);
    cudaGetSymbolAddress((void**)&op2, g_o2);
    cudaGetSymbolAddress((void**)&xh, g_xh);
    cudaGetSymbolAddress((void**)&xm, g_xm);
    cudaGetSymbolAddress((void**)&wh, g_wh);
    cudaGetSymbolAddress((void**)&wm, g_wm);
    cudaGetSymbolAddress((void**)&ahp, g_ah);
    cudaGetSymbolAddress((void**)&amp, g_am);

    cudaFuncSetAttribute(gemm_bf16s_kernel,
                         cudaFuncAttributeMaxDynamicSharedMemorySize, DSM_BYTES);

    // 1) Split x and weights into bf16 hi/mid (single launch)
    int nblk = XN / 1024 + 4 * WN / 1024;     // 768 + 576 = 1344
    split_kernel<<<nblk, 256>>>(x, Wq, Wk, Wv, Wo, xh, xm, wh, wm);

    // 2) Fused Q,K,V projections, split-K=2: grid (18, 32, 2) = 1152 CTAs
    dim3 qkv_grid(3 * (C / 64), NTOT / 64, 2);
    gemm_bf16s_kernel<<<qkv_grid, 128, DSM_BYTES>>>(
        xh, xm, wh, wm, bq, bk, bv,
        qp, kp, vp, qp2, kp2, vp2, C, C);

    // 3) Attention with fused RoPE + split-K reduce of q,k,v
    attn_kernel<<<dim3(GH / 4, NGR), 256>>>(pos, rfreq);

    // 4) Output projection, split-K=2: grid (6, 32, 2) = 384 CTAs
    dim3 o_grid(C / 64, NTOT / 64, 2);
    gemm_bf16s_kernel<<<o_grid, 128, DSM_BYTES>>>(
        ahp, amp, wh + 3 * WN, wm + 3 * WN, bo, bo, bo,
        out, out, out, op2, op2, op2, C, C);

    // 5) Reduce: out += z=1 partial
    addp_kernel<<<XN / 1024, 256>>>(out, op2);
}

// round 11
// speedup vs baseline: 1.1006x; 1.1006x over previous
#include <cuda_runtime.h>
#include <cuda_bf16.h>
#include <mma.h>
#include <cstdint>

using namespace nvcuda;

// Problem constants (fixed by the reference)
#define NTOT   2048
#define NGR    32
#define NPG    64
#define C      384
#define G12    12
#define HEFF   2
#define GH     24
#define HD     16

#define XN (NTOT * C)        // 786432
#define WN (C * C)           // 147456

// Scratch (device globals — no allocation allowed)
__device__ float g_q[XN];
__device__ float g_k[XN];
__device__ float g_v[XN];
__device__ __nv_bfloat16 g_xh[XN];
__device__ __nv_bfloat16 g_xm[XN];
__device__ __nv_bfloat16 g_wh[4 * WN];   // Wq | Wk | Wv | Wo  (row-major [K,N])
__device__ __nv_bfloat16 g_wm[4 * WN];
__device__ __nv_bfloat16 g_ah[XN];       // attention output hi
__device__ __nv_bfloat16 g_am[XN];       // attention output mid

// ---------------------------------------------------------------------------
// cp.async helpers
// ---------------------------------------------------------------------------
__device__ __forceinline__ void cp16(unsigned int dst, const void* src) {
    asm volatile("cp.async.cg.shared.global [%0], [%1], 16;\n" :: "r"(dst), "l"(src));
}
__device__ __forceinline__ void cp_commit() {
    asm volatile("cp.async.commit_group;\n");
}
template <int N>
__device__ __forceinline__ void cp_wait() {
    asm volatile("cp.async.wait_group %0;\n" :: "n"(N));
}

// ---------------------------------------------------------------------------
// One-shot split: x and the 4 weight matrices -> bf16 hi + mid.
// ---------------------------------------------------------------------------
__global__ __launch_bounds__(256) void split_kernel(
    const float* __restrict__ x,
    const float* __restrict__ wq, const float* __restrict__ wk,
    const float* __restrict__ wv, const float* __restrict__ wo,
    __nv_bfloat16* __restrict__ xh, __nv_bfloat16* __restrict__ xm,
    __nv_bfloat16* __restrict__ wh, __nv_bfloat16* __restrict__ wm)
{
    const int bid = blockIdx.x;
    const float* src;
    __nv_bfloat16 *dh, *dm;
    int loc;
    if (bid < XN / 1024) {
        loc = (bid * 256 + threadIdx.x) * 4;
        src = x; dh = xh; dm = xm;
    } else {
        int w = ((bid - XN / 1024) * 256 + threadIdx.x) * 4;   // [0, 4*WN)
        int m = w / WN;
        loc = w - m * WN;
        src = (m == 0) ? wq : (m == 1) ? wk : (m == 2) ? wv : wo;
        dh = wh + m * WN; dm = wm + m * WN;
    }
    float4 v4 = *reinterpret_cast<const float4*>(&src[loc]);
    float v[4] = {v4.x, v4.y, v4.z, v4.w};
    __nv_bfloat16 h[4], m_[4];
    #pragma unroll
    for (int e = 0; e < 4; e++) {
        h[e]  = __float2bfloat16(v[e]);
        m_[e] = __float2bfloat16(v[e] - __bfloat162float(h[e]));
    }
    __nv_bfloat162 hp0(h[0], h[1]), hp1(h[2], h[3]);
    __nv_bfloat162 mp0(m_[0], m_[1]), mp1(m_[2], m_[3]);
    *reinterpret_cast<uint2*>(&dh[loc]) = make_uint2(
        *reinterpret_cast<unsigned*>(&hp0), *reinterpret_cast<unsigned*>(&hp1));
    *reinterpret_cast<uint2*>(&dm[loc]) = make_uint2(
        *reinterpret_cast<unsigned*>(&mp0), *reinterpret_cast<unsigned*>(&mp1));
}

// ---------------------------------------------------------------------------
// In-CTA split-K wmma GEMM on pre-split bf16 (hi+mid, 3 MMA products):
//   O[M,N] = A[M,K] @ W[K,N] + bias  (fp32 out)
// BM=64, BN=64, BK=64 per iter. 256 threads = 8 warps:
//   warps 0-3 accumulate k in [it*64, it*64+32), warps 4-7 [it*64+32, +64);
//   each warp owns a 32x32 output quadrant. Partials merge via smem epilogue.
// 2-stage cp.async ring. blockIdx.x selects weight matrix (QKV fusion).
// ---------------------------------------------------------------------------
#define TST 72                       // smem tile row stride (elems) = 144B
#define AH_O 0
#define AM_O 9216                    // 64*144
#define BH_O 18432
#define BM_O 27648
#define STG_BYTES 36864
#define DSM_BYTES (2 * STG_BYTES)    // 73728

__global__ __launch_bounds__(256, 2) void gemm_bf16s_kernel(
    const __nv_bfloat16* __restrict__ Ah, const __nv_bfloat16* __restrict__ Am,
    const __nv_bfloat16* __restrict__ Wh, const __nv_bfloat16* __restrict__ Wm,
    const float* __restrict__ bias0, const float* __restrict__ bias1, const float* __restrict__ bias2,
    float* __restrict__ O0, float* __restrict__ O1, float* __restrict__ O2,
    int K, int N)
{
    const int ntiles = N >> 6;
    const int which = blockIdx.x / ntiles;
    const int bc    = blockIdx.x % ntiles;
    const int br    = blockIdx.y;

    const __nv_bfloat16* Bh = Wh + (long)which * K * N;
    const __nv_bfloat16* Bm = Wm + (long)which * K * N;
    const float* bias = (which == 0) ? bias0 : (which == 1) ? bias1 : bias2;
    float*       O    = (which == 0) ? O0    : (which == 1) ? O1    : O2;

    extern __shared__ __align__(16) unsigned char dsm[];
    const unsigned int sbase = (unsigned int)__cvta_generic_to_shared(dsm);

    const int tid  = threadIdx.x;
    const int warp = tid >> 5;
    const int kg   = warp >> 2;          // K-group 0/1 (within-tile 32-el halves)
    const int wr   = (warp >> 1) & 1;    // 32-row band
    const int wc   = warp & 1;           // 32-col band

    const int niter = K >> 6;            // 6 for K=384

    // Per-thread load coords: each tile (64x64 bf16) = 512 x 16B segs,
    // 2 per thread per split. r = s>>3 (row), c = s&7 (16B column).
    const int r0 = tid >> 3,           c0 = (tid & 7) * 16;
    const int r1 = (tid + 256) >> 3,   c1 = ((tid + 256) & 7) * 16;

    const __nv_bfloat16* agh0 = Ah + (long)(br * 64 + r0) * K + (c0 >> 1);
    const __nv_bfloat16* agh1 = Ah + (long)(br * 64 + r1) * K + (c1 >> 1);
    const __nv_bfloat16* agm0 = Am + (long)(br * 64 + r0) * K + (c0 >> 1);
    const __nv_bfloat16* agm1 = Am + (long)(br * 64 + r1) * K + (c1 >> 1);
    const __nv_bfloat16* bgh0 = Bh + (long)r0 * N + bc * 64 + (c0 >> 1);
    const __nv_bfloat16* bgh1 = Bh + (long)r1 * N + bc * 64 + (c1 >> 1);
    const __nv_bfloat16* bgm0 = Bm + (long)r0 * N + bc * 64 + (c0 >> 1);
    const __nv_bfloat16* bgm1 = Bm + (long)r1 * N + bc * 64 + (c1 >> 1);

    const unsigned int sa0 = r0 * (TST * 2) + c0;
    const unsigned int sa1 = r1 * (TST * 2) + c1;

    auto load_stage = [&](int stg, int it) {
        const unsigned sb = sbase + stg * STG_BYTES;
        const int ko = it * 64;               // A column advance (elements)
        const long bko = (long)it * 64 * N;   // B row advance
        cp16(sb + AH_O + sa0, agh0 + ko);
        cp16(sb + AH_O + sa1, agh1 + ko);
        cp16(sb + AM_O + sa0, agm0 + ko);
        cp16(sb + AM_O + sa1, agm1 + ko);
        cp16(sb + BH_O + sa0, bgh0 + bko);
        cp16(sb + BH_O + sa1, bgh1 + bko);
        cp16(sb + BM_O + sa0, bgm0 + bko);
        cp16(sb + BM_O + sa1, bgm1 + bko);
        cp_commit();
    };

    load_stage(0, 0);
    if (niter > 1) load_stage(1, 1);

    wmma::fragment<wmma::accumulator, 16, 16, 16, float> acc[2][2];
    #pragma unroll
    for (int i = 0; i < 2; i++)
        #pragma unroll
        for (int j = 0; j < 2; j++)
            wmma::fill_fragment(acc[i][j], 0.0f);

    for (int it = 0; it < niter; it++) {
        const int s = it & 1;
        if (it + 1 < niter) { cp_wait<1>(); } else { cp_wait<0>(); }
        __syncthreads();

        const __nv_bfloat16* ash = reinterpret_cast<const __nv_bfloat16*>(dsm + s * STG_BYTES + AH_O);
        const __nv_bfloat16* asm_ = reinterpret_cast<const __nv_bfloat16*>(dsm + s * STG_BYTES + AM_O);
        const __nv_bfloat16* bsh = reinterpret_cast<const __nv_bfloat16*>(dsm + s * STG_BYTES + BH_O);
        const __nv_bfloat16* bsm = reinterpret_cast<const __nv_bfloat16*>(dsm + s * STG_BYTES + BM_O);

        #pragma unroll
        for (int ks = 0; ks < 2; ks++) {
            const int k16 = kg * 32 + ks * 16;
            wmma::fragment<wmma::matrix_a, 16, 16, 16, __nv_bfloat16, wmma::row_major> ah[2], am[2];
            wmma::fragment<wmma::matrix_b, 16, 16, 16, __nv_bfloat16, wmma::row_major> bh[2], bm[2];
            #pragma unroll
            for (int i = 0; i < 2; i++) {
                wmma::load_matrix_sync(ah[i], ash + (wr * 32 + i * 16) * TST + k16, TST);
                wmma::load_matrix_sync(am[i], asm_ + (wr * 32 + i * 16) * TST + k16, TST);
            }
            #pragma unroll
            for (int j = 0; j < 2; j++) {
                wmma::load_matrix_sync(bh[j], bsh + k16 * TST + wc * 32 + j * 16, TST);
                wmma::load_matrix_sync(bm[j], bsm + k16 * TST + wc * 32 + j * 16, TST);
            }
            #pragma unroll
            for (int i = 0; i < 2; i++)
                #pragma unroll
                for (int j = 0; j < 2; j++)
                    wmma::mma_sync(acc[i][j], ah[i], bh[j], acc[i][j]);
            #pragma unroll
            for (int i = 0; i < 2; i++)
                #pragma unroll
                for (int j = 0; j < 2; j++)
                    wmma::mma_sync(acc[i][j], ah[i], bm[j], acc[i][j]);
            #pragma unroll
            for (int i = 0; i < 2; i++)
                #pragma unroll
                for (int j = 0; j < 2; j++)
                    wmma::mma_sync(acc[i][j], am[i], bh[j], acc[i][j]);
        }
        __syncthreads();
        if (it + 2 < niter) load_stage(s, it + 2);
    }

    // Epilogue: two K-group partials -> smem -> summed, +bias, coalesced out
    float (*Cs0)[64] = reinterpret_cast<float(*)[64]>(dsm);
    float (*Cs1)[64] = reinterpret_cast<float(*)[64]>(dsm + 16384);
    float (*Cbuf)[64] = (kg == 0) ? Cs0 : Cs1;
    #pragma unroll
    for (int i = 0; i < 2; i++)
        #pragma unroll
        for (int j = 0; j < 2; j++)
            wmma::store_matrix_sync(&Cbuf[wr * 32 + i * 16][wc * 32 + j * 16],
                                    acc[i][j], 64, wmma::mem_row_major);
    __syncthreads();

    #pragma unroll
    for (int l = 0; l < 16; l++) {
        int idx = tid + l * 256;
        int r = idx >> 6, c = idx & 63;
        O[(long)(br * 64 + r) * N + bc * 64 + c] =
            Cs0[r][c] + Cs1[r][c] + bias[bc * 64 + c];
    }
}

// ---------------------------------------------------------------------------
// Dense attention per (graph, group-head), RoPE fused. Single-pass softmax.
// Writes bf16 hi/mid for the O-projection GEMM.
// ---------------------------------------------------------------------------
__global__ __launch_bounds__(256) void attn_kernel(const float* __restrict__ pos,
                                                   const float* __restrict__ freqs)
{
    const int sub   = threadIdx.x >> 6;
    const int i     = threadIdx.x & 63;
    const int gh    = blockIdx.x * 4 + sub;
    const int graph = blockIdx.y;
    const int h     = gh & 1;

    __shared__ float Ks[4][64][16];
    __shared__ float Vs[4][64][16];

    const int node = graph * NPG + i;
    const int off  = node * C + gh * HD;

    float qr[16], kr[16];
    {
        const float4* qp = reinterpret_cast<const float4*>(g_q + off);
        const float4* kp = reinterpret_cast<const float4*>(g_k + off);
        const float4* vp = reinterpret_cast<const float4*>(g_v + off);
        float4* vs = reinterpret_cast<float4*>(&Vs[sub][i][0]);
        #pragma unroll
        for (int t = 0; t < 4; t++) {
            float4 qv = qp[t];
            qr[4*t+0] = qv.x; qr[4*t+1] = qv.y; qr[4*t+2] = qv.z; qr[4*t+3] = qv.w;
            float4 kv = kp[t];
            kr[4*t+0] = kv.x; kr[4*t+1] = kv.y; kr[4*t+2] = kv.z; kr[4*t+3] = kv.w;
            vs[t] = vp[t];
        }
    }

    const float p0 = pos[node * 3 + 0];
    const float p1 = pos[node * 3 + 1];
    const float p2 = pos[node * 3 + 2];
    #pragma unroll
    for (int f = 0; f < 8; f++) {
        float th = p0 * freqs[ 0 + h * 8 + f]
                 + p1 * freqs[16 + h * 8 + f]
                 + p2 * freqs[32 + h * 8 + f];
        float s, c;
        __sincosf(th, &s, &c);
        float q1 = qr[2*f], q2 = qr[2*f+1];
        qr[2*f]   = q1 * c - q2 * s;
        qr[2*f+1] = q1 * s + q2 * c;
        float k1 = kr[2*f], k2 = kr[2*f+1];
        kr[2*f]   = k1 * c - k2 * s;
        kr[2*f+1] = k1 * s + k2 * c;
    }
    #pragma unroll
    for (int d = 0; d < 16; d++) qr[d] *= 0.25f;
    #pragma unroll
    for (int d = 0; d < 16; d++) Ks[sub][i][d] = kr[d];
    __syncthreads();

    float den = 0.f;
    float o[16] = {};
    #pragma unroll 2
    for (int j = 0; j < 64; j++) {
        float s = 0.f;
        #pragma unroll
        for (int d = 0; d < 16; d++) s = fmaf(qr[d], Ks[sub][j][d], s);
        float e = __expf(s);
        den += e;
        #pragma unroll
        for (int d = 0; d < 16; d++) o[d] = fmaf(e, Vs[sub][j][d], o[d]);
    }
    float inv = 1.f / den;

    __nv_bfloat16 hb[16], mb[16];
    #pragma unroll
    for (int d = 0; d < 16; d++) {
        float val = o[d] * inv;
        hb[d] = __float2bfloat16(val);
        mb[d] = __float2bfloat16(val - __bfloat162float(hb[d]));
    }
    uint4 uh0, uh1, um0, um1;
    unsigned* uhp0 = &uh0.x; unsigned* uhp1 = &uh1.x;
    unsigned* ump0 = &um0.x; unsigned* ump1 = &um1.x;
    #pragma unroll
    for (int t = 0; t < 4; t++) {
        __nv_bfloat162 a(hb[2*t], hb[2*t+1]);       uhp0[t] = *reinterpret_cast<unsigned*>(&a);
        __nv_bfloat162 b(hb[8+2*t], hb[8+2*t+1]);   uhp1[t] = *reinterpret_cast<unsigned*>(&b);
        __nv_bfloat162 c2(mb[2*t], mb[2*t+1]);      ump0[t] = *reinterpret_cast<unsigned*>(&c2);
        __nv_bfloat162 d2(mb[8+2*t], mb[8+2*t+1]);  ump1[t] = *reinterpret_cast<unsigned*>(&d2);
    }
    uint4* ah = reinterpret_cast<uint4*>(&g_ah[off]);
    uint4* am = reinterpret_cast<uint4*>(&g_am[off]);
    ah[0] = uh0; ah[1] = uh1;
    am[0] = um0; am[1] = um1;
}

// ---------------------------------------------------------------------------
extern "C" void kernel_launch(void* const* d_in, const int* in_sizes, int n_in,
                              void* d_out, int out_size)
{
    const float* x     = (const float*)d_in[0];
    const float* pos   = (const float*)d_in[1];
    const float* Wq    = (const float*)d_in[2];
    const float* bq    = (const float*)d_in[3];
    const float* Wk    = (const float*)d_in[4];
    const float* bk    = (const float*)d_in[5];
    const float* Wv    = (const float*)d_in[6];
    const float* bv    = (const float*)d_in[7];
    const float* Wo    = (const float*)d_in[8];
    const float* bo    = (const float*)d_in[9];
    const float* rfreq = (const float*)d_in[10];
    float* out = (float*)d_out;

    float *qp, *kp, *vp;
    __nv_bfloat16 *xh, *xm, *wh, *wm, *ahp, *amp;
    cudaGetSymbolAddress((void**)&qp, g_q);
    cudaGetSymbolAddress((void**)&kp, g_k);
    cudaGetSymbolAddress((void**)&vp, g_v);
    cudaGetSymbolAddress((void**)&xh, g_xh);
    cudaGetSymbolAddress((void**)&xm, g_xm);
    cudaGetSymbolAddress((void**)&wh, g_wh);
    cudaGetSymbolAddress((void**)&wm, g_wm);
    cudaGetSymbolAddress((void**)&ahp, g_ah);
    cudaGetSymbolAddress((void**)&amp, g_am);

    cudaFuncSetAttribute(gemm_bf16s_kernel,
                         cudaFuncAttributeMaxDynamicSharedMemorySize, DSM_BYTES);

    // 1) Split x and weights into bf16 hi/mid (single launch)
    int nblk = XN / 1024 + 4 * WN / 1024;     // 1344
    split_kernel<<<nblk, 256>>>(x, Wq, Wk, Wv, Wo, xh, xm, wh, wm);

    // 2) Fused Q,K,V projections: grid (18, 32) = 576 CTAs x 256 threads
    dim3 qkv_grid(3 * (C / 64), NTOT / 64);
    gemm_bf16s_kernel<<<qkv_grid, 256, DSM_BYTES>>>(
        xh, xm, wh, wm, bq, bk, bv, qp, kp, vp, C, C);

    // 3) Attention with fused RoPE
    attn_kernel<<<dim3(GH / 4, NGR), 256>>>(pos, rfreq);

    // 4) Output projection: grid (6, 32) = 192 CTAs
    dim3 o_grid(C / 64, NTOT / 64);
    gemm_bf16s_kernel<<<o_grid, 256, DSM_BYTES>>>(
        ahp, amp, wh + 3 * WN, wm + 3 * WN, bo, bo, bo,
        out, out, out, C, C);
}

// round 12
// speedup vs baseline: 1.1370x; 1.0331x over previous
#include <cuda_runtime.h>
#include <cuda_bf16.h>
#include <mma.h>
#include <cstdint>

using namespace nvcuda;

// Problem constants (fixed by the reference)
#define NTOT   2048
#define NGR    32
#define NPG    64
#define C      384
#define G12    12
#define HEFF   2
#define GH     24
#define HD     16

#define XN (NTOT * C)        // 786432
#define WN (C * C)           // 147456

// Scratch (device globals — no allocation allowed)
__device__ float g_q[XN];
__device__ float g_k[XN];
__device__ float g_v[XN];
__device__ __nv_bfloat16 g_xh[XN];
__device__ __nv_bfloat16 g_xm[XN];
__device__ __nv_bfloat16 g_wh[4 * WN];   // Wq | Wk | Wv | Wo  (row-major [K,N])
__device__ __nv_bfloat16 g_wm[4 * WN];
__device__ __nv_bfloat16 g_ah[XN];       // attention output hi
__device__ __nv_bfloat16 g_am[XN];       // attention output mid
__device__ int g_c1[NGR];                // QKV-done counters (18 per graph)
__device__ int g_c2[NGR];                // attn-done counters (6 per graph)

// ---------------------------------------------------------------------------
// cp.async helpers
// ---------------------------------------------------------------------------
__device__ __forceinline__ void cp16(unsigned int dst, const void* src) {
    asm volatile("cp.async.cg.shared.global [%0], [%1], 16;\n" :: "r"(dst), "l"(src));
}
__device__ __forceinline__ void cp_commit() {
    asm volatile("cp.async.commit_group;\n");
}
template <int N>
__device__ __forceinline__ void cp_wait() {
    asm volatile("cp.async.wait_group %0;\n" :: "n"(N));
}

// ---------------------------------------------------------------------------
// One-shot split: x and the 4 weight matrices -> bf16 hi + mid.
// Block 0 also resets the dataflow counters (this kernel fully completes
// before the mega kernel starts, so the reset is safely ordered).
// ---------------------------------------------------------------------------
__global__ __launch_bounds__(256) void split_kernel(
    const float* __restrict__ x,
    const float* __restrict__ wq, const float* __restrict__ wk,
    const float* __restrict__ wv, const float* __restrict__ wo,
    __nv_bfloat16* __restrict__ xh, __nv_bfloat16* __restrict__ xm,
    __nv_bfloat16* __restrict__ wh, __nv_bfloat16* __restrict__ wm)
{
    const int bid = blockIdx.x;
    if (bid == 0 && threadIdx.x < 2 * NGR) {
        if (threadIdx.x < NGR) g_c1[threadIdx.x] = 0;
        else                   g_c2[threadIdx.x - NGR] = 0;
    }
    const float* src;
    __nv_bfloat16 *dh, *dm;
    int loc;
    if (bid < XN / 1024) {
        loc = (bid * 256 + threadIdx.x) * 4;
        src = x; dh = xh; dm = xm;
    } else {
        int w = ((bid - XN / 1024) * 256 + threadIdx.x) * 4;   // [0, 4*WN)
        int m = w / WN;
        loc = w - m * WN;
        src = (m == 0) ? wq : (m == 1) ? wk : (m == 2) ? wv : wo;
        dh = wh + m * WN; dm = wm + m * WN;
    }
    float4 v4 = *reinterpret_cast<const float4*>(&src[loc]);
    float v[4] = {v4.x, v4.y, v4.z, v4.w};
    __nv_bfloat16 h[4], m_[4];
    #pragma unroll
    for (int e = 0; e < 4; e++) {
        h[e]  = __float2bfloat16(v[e]);
        m_[e] = __float2bfloat16(v[e] - __bfloat162float(h[e]));
    }
    __nv_bfloat162 hp0(h[0], h[1]), hp1(h[2], h[3]);
    __nv_bfloat162 mp0(m_[0], m_[1]), mp1(m_[2], m_[3]);
    *reinterpret_cast<uint2*>(&dh[loc]) = make_uint2(
        *reinterpret_cast<unsigned*>(&hp0), *reinterpret_cast<unsigned*>(&hp1));
    *reinterpret_cast<uint2*>(&dm[loc]) = make_uint2(
        *reinterpret_cast<unsigned*>(&mp0), *reinterpret_cast<unsigned*>(&mp1));
}

// ---------------------------------------------------------------------------
// GEMM tile device function (R11 design, in-CTA split-K over 8 warps):
//   O[br*64:+64, bc*64:+64] = A @ B + bias. 256 threads, BK=64/iter,
//   2-stage cp.async ring, hi/mid bf16 3-product accumulate.
// ---------------------------------------------------------------------------
#define TST 72                       // smem tile row stride (elems) = 144B
#define AH_O 0
#define AM_O 9216                    // 64*144
#define BH_O 18432
#define BM_O 27648
#define STG_BYTES 36864
#define DSM_BYTES (2 * STG_BYTES)    // 73728

__device__ __forceinline__ void gemm_tile(
    unsigned char* dsm,
    const __nv_bfloat16* __restrict__ Ah, const __nv_bfloat16* __restrict__ Am,
    const __nv_bfloat16* __restrict__ Bh, const __nv_bfloat16* __restrict__ Bm,
    const float* __restrict__ bias, float* __restrict__ O,
    int br, int bc, int K, int N)
{
    const unsigned int sbase = (unsigned int)__cvta_generic_to_shared(dsm);
    const int tid  = threadIdx.x;
    const int warp = tid >> 5;
    const int kg   = warp >> 2;
    const int wr   = (warp >> 1) & 1;
    const int wc   = warp & 1;
    const int niter = K >> 6;

    const int r0 = tid >> 3,           c0 = (tid & 7) * 16;
    const int r1 = (tid + 256) >> 3,   c1 = ((tid + 256) & 7) * 16;

    const __nv_bfloat16* agh0 = Ah + (long)(br * 64 + r0) * K + (c0 >> 1);
    const __nv_bfloat16* agh1 = Ah + (long)(br * 64 + r1) * K + (c1 >> 1);
    const __nv_bfloat16* agm0 = Am + (long)(br * 64 + r0) * K + (c0 >> 1);
    const __nv_bfloat16* agm1 = Am + (long)(br * 64 + r1) * K + (c1 >> 1);
    const __nv_bfloat16* bgh0 = Bh + (long)r0 * N + bc * 64 + (c0 >> 1);
    const __nv_bfloat16* bgh1 = Bh + (long)r1 * N + bc * 64 + (c1 >> 1);
    const __nv_bfloat16* bgm0 = Bm + (long)r0 * N + bc * 64 + (c0 >> 1);
    const __nv_bfloat16* bgm1 = Bm + (long)r1 * N + bc * 64 + (c1 >> 1);

    const unsigned int sa0 = r0 * (TST * 2) + c0;
    const unsigned int sa1 = r1 * (TST * 2) + c1;

    auto load_stage = [&](int stg, int it) {
        const unsigned sb = sbase + stg * STG_BYTES;
        const int ko = it * 64;
        const long bko = (long)it * 64 * N;
        cp16(sb + AH_O + sa0, agh0 + ko);
        cp16(sb + AH_O + sa1, agh1 + ko);
        cp16(sb + AM_O + sa0, agm0 + ko);
        cp16(sb + AM_O + sa1, agm1 + ko);
        cp16(sb + BH_O + sa0, bgh0 + bko);
        cp16(sb + BH_O + sa1, bgh1 + bko);
        cp16(sb + BM_O + sa0, bgm0 + bko);
        cp16(sb + BM_O + sa1, bgm1 + bko);
        cp_commit();
    };

    load_stage(0, 0);
    if (niter > 1) load_stage(1, 1);

    wmma::fragment<wmma::accumulator, 16, 16, 16, float> acc[2][2];
    #pragma unroll
    for (int i = 0; i < 2; i++)
        #pragma unroll
        for (int j = 0; j < 2; j++)
            wmma::fill_fragment(acc[i][j], 0.0f);

    for (int it = 0; it < niter; it++) {
        const int s = it & 1;
        if (it + 1 < niter) { cp_wait<1>(); } else { cp_wait<0>(); }
        __syncthreads();

        const __nv_bfloat16* ash = reinterpret_cast<const __nv_bfloat16*>(dsm + s * STG_BYTES + AH_O);
        const __nv_bfloat16* asm_ = reinterpret_cast<const __nv_bfloat16*>(dsm + s * STG_BYTES + AM_O);
        const __nv_bfloat16* bsh = reinterpret_cast<const __nv_bfloat16*>(dsm + s * STG_BYTES + BH_O);
        const __nv_bfloat16* bsm = reinterpret_cast<const __nv_bfloat16*>(dsm + s * STG_BYTES + BM_O);

        #pragma unroll
        for (int ks = 0; ks < 2; ks++) {
            const int k16 = kg * 32 + ks * 16;
            wmma::fragment<wmma::matrix_a, 16, 16, 16, __nv_bfloat16, wmma::row_major> ah[2], am[2];
            wmma::fragment<wmma::matrix_b, 16, 16, 16, __nv_bfloat16, wmma::row_major> bh[2], bm[2];
            #pragma unroll
            for (int i = 0; i < 2; i++) {
                wmma::load_matrix_sync(ah[i], ash + (wr * 32 + i * 16) * TST + k16, TST);
                wmma::load_matrix_sync(am[i], asm_ + (wr * 32 + i * 16) * TST + k16, TST);
            }
            #pragma unroll
            for (int j = 0; j < 2; j++) {
                wmma::load_matrix_sync(bh[j], bsh + k16 * TST + wc * 32 + j * 16, TST);
                wmma::load_matrix_sync(bm[j], bsm + k16 * TST + wc * 32 + j * 16, TST);
            }
            #pragma unroll
            for (int i = 0; i < 2; i++)
                #pragma unroll
                for (int j = 0; j < 2; j++)
                    wmma::mma_sync(acc[i][j], ah[i], bh[j], acc[i][j]);
            #pragma unroll
            for (int i = 0; i < 2; i++)
                #pragma unroll
                for (int j = 0; j < 2; j++)
                    wmma::mma_sync(acc[i][j], ah[i], bm[j], acc[i][j]);
            #pragma unroll
            for (int i = 0; i < 2; i++)
                #pragma unroll
                for (int j = 0; j < 2; j++)
                    wmma::mma_sync(acc[i][j], am[i], bh[j], acc[i][j]);
        }
        __syncthreads();
        if (it + 2 < niter) load_stage(s, it + 2);
    }

    float (*Cs0)[64] = reinterpret_cast<float(*)[64]>(dsm);
    float (*Cs1)[64] = reinterpret_cast<float(*)[64]>(dsm + 16384);
    float (*Cbuf)[64] = (kg == 0) ? Cs0 : Cs1;
    #pragma unroll
    for (int i = 0; i < 2; i++)
        #pragma unroll
        for (int j = 0; j < 2; j++)
            wmma::store_matrix_sync(&Cbuf[wr * 32 + i * 16][wc * 32 + j * 16],
                                    acc[i][j], 64, wmma::mem_row_major);
    __syncthreads();

    #pragma unroll
    for (int l = 0; l < 16; l++) {
        int idx = tid + l * 256;
        int r = idx >> 6, c = idx & 63;
        O[(long)(br * 64 + r) * N + bc * 64 + c] =
            Cs0[r][c] + Cs1[r][c] + bias[bc * 64 + c];
    }
}

// ---------------------------------------------------------------------------
// Mega kernel: QKV GEMM (bids 0..575) -> attention (576..767) -> O GEMM
// (768..959) in ONE launch. Cross-phase sync via per-graph atomic counters;
// CTAs dispatch in increasing bid order, producers never wait on consumers.
// ---------------------------------------------------------------------------
__global__ __launch_bounds__(256, 2) void mega_kernel(
    const float* __restrict__ pos, const float* __restrict__ freqs,
    const float* __restrict__ bq, const float* __restrict__ bk,
    const float* __restrict__ bv, const float* __restrict__ bo,
    float* __restrict__ out)
{
    extern __shared__ __align__(16) unsigned char dsm[];
    const int bid = blockIdx.x;
    const int tid = threadIdx.x;

    if (bid < 576) {
        // ---- QKV projection: g = graph/row-tile, 18 CTAs per graph ----
        const int g     = bid / 18;
        const int rem   = bid % 18;
        const int which = rem / 6;
        const int bc    = rem % 6;
        const __nv_bfloat16* Bh = g_wh + (long)which * WN;
        const __nv_bfloat16* Bm = g_wm + (long)which * WN;
        const float* bias = (which == 0) ? bq : (which == 1) ? bk : bv;
        float* O = (which == 0) ? g_q : (which == 1) ? g_k : g_v;
        gemm_tile(dsm, g_xh, g_xm, Bh, Bm, bias, O, g, bc, C, C);
        __threadfence();
        __syncthreads();
        if (tid == 0) atomicAdd(&g_c1[g], 1);

    } else if (bid < 768) {
        // ---- Attention (RoPE fused), 6 CTAs per graph, 4 gh each ----
        const int a     = bid - 576;
        const int graph = a / 6;
        const int blk   = a % 6;
        const int sub   = tid >> 6;
        const int i     = tid & 63;
        const int gh    = blk * 4 + sub;
        const int h     = gh & 1;

        // Wait for this graph's QKV tiles
        if (tid == 0) {
            while (atomicAdd(&g_c1[graph], 0) < 18) __nanosleep(64);
        }
        __syncthreads();
        __threadfence();

        float (*Ks)[64][16] = reinterpret_cast<float(*)[64][16]>(dsm);
        float (*Vs)[64][16] = reinterpret_cast<float(*)[64][16]>(dsm + 16384);

        const int node = graph * NPG + i;
        const int off  = node * C + gh * HD;

        float qr[16], kr[16];
        {
            const float4* qp = reinterpret_cast<const float4*>(g_q + off);
            const float4* kp = reinterpret_cast<const float4*>(g_k + off);
            const float4* vp = reinterpret_cast<const float4*>(g_v + off);
            float4* vs = reinterpret_cast<float4*>(&Vs[sub][i][0]);
            #pragma unroll
            for (int t = 0; t < 4; t++) {
                float4 qv = qp[t];
                qr[4*t+0] = qv.x; qr[4*t+1] = qv.y; qr[4*t+2] = qv.z; qr[4*t+3] = qv.w;
                float4 kv = kp[t];
                kr[4*t+0] = kv.x; kr[4*t+1] = kv.y; kr[4*t+2] = kv.z; kr[4*t+3] = kv.w;
                vs[t] = vp[t];
            }
        }

        const float p0 = pos[node * 3 + 0];
        const float p1 = pos[node * 3 + 1];
        const float p2 = pos[node * 3 + 2];
        #pragma unroll
        for (int f = 0; f < 8; f++) {
            float th = p0 * freqs[ 0 + h * 8 + f]
                     + p1 * freqs[16 + h * 8 + f]
                     + p2 * freqs[32 + h * 8 + f];
            float s, c;
            __sincosf(th, &s, &c);
            float q1 = qr[2*f], q2 = qr[2*f+1];
            qr[2*f]   = q1 * c - q2 * s;
            qr[2*f+1] = q1 * s + q2 * c;
            float k1 = kr[2*f], k2 = kr[2*f+1];
            kr[2*f]   = k1 * c - k2 * s;
            kr[2*f+1] = k1 * s + k2 * c;
        }
        #pragma unroll
        for (int d = 0; d < 16; d++) qr[d] *= 0.25f;
        #pragma unroll
        for (int d = 0; d < 16; d++) Ks[sub][i][d] = kr[d];
        __syncthreads();

        float den = 0.f;
        float o[16] = {};
        #pragma unroll 2
        for (int j = 0; j < 64; j++) {
            float s = 0.f;
            #pragma unroll
            for (int d = 0; d < 16; d++) s = fmaf(qr[d], Ks[sub][j][d], s);
            float e = __expf(s);
            den += e;
            #pragma unroll
            for (int d = 0; d < 16; d++) o[d] = fmaf(e, Vs[sub][j][d], o[d]);
        }
        float inv = 1.f / den;

        __nv_bfloat16 hb[16], mb[16];
        #pragma unroll
        for (int d = 0; d < 16; d++) {
            float val = o[d] * inv;
            hb[d] = __float2bfloat16(val);
            mb[d] = __float2bfloat16(val - __bfloat162float(hb[d]));
        }
        uint4 uh0, uh1, um0, um1;
        unsigned* uhp0 = &uh0.x; unsigned* uhp1 = &uh1.x;
        unsigned* ump0 = &um0.x; unsigned* ump1 = &um1.x;
        #pragma unroll
        for (int t = 0; t < 4; t++) {
            __nv_bfloat162 a2(hb[2*t], hb[2*t+1]);      uhp0[t] = *reinterpret_cast<unsigned*>(&a2);
            __nv_bfloat162 b2(hb[8+2*t], hb[8+2*t+1]);  uhp1[t] = *reinterpret_cast<unsigned*>(&b2);
            __nv_bfloat162 c2(mb[2*t], mb[2*t+1]);      ump0[t] = *reinterpret_cast<unsigned*>(&c2);
            __nv_bfloat162 d2(mb[8+2*t], mb[8+2*t+1]);  ump1[t] = *reinterpret_cast<unsigned*>(&d2);
        }
        uint4* ahp = reinterpret_cast<uint4*>(&g_ah[off]);
        uint4* amp = reinterpret_cast<uint4*>(&g_am[off]);
        ahp[0] = uh0; ahp[1] = uh1;
        amp[0] = um0; amp[1] = um1;

        __threadfence();
        __syncthreads();
        if (tid == 0) atomicAdd(&g_c2[graph], 1);

    } else {
        // ---- Output projection: row-tile = graph, 6 CTAs per graph ----
        const int o  = bid - 768;
        const int br = o / 6;
        const int bc = o % 6;

        if (tid == 0) {
            while (atomicAdd(&g_c2[br], 0) < 6) __nanosleep(64);
        }
        __syncthreads();
        __threadfence();

        gemm_tile(dsm, g_ah, g_am, g_wh + 3L * WN, g_wm + 3L * WN,
                  bo, out, br, bc, C, C);
    }
}

// ---------------------------------------------------------------------------
extern "C" void kernel_launch(void* const* d_in, const int* in_sizes, int n_in,
                              void* d_out, int out_size)
{
    const float* x     = (const float*)d_in[0];
    const float* pos   = (const float*)d_in[1];
    const float* Wq    = (const float*)d_in[2];
    const float* bq    = (const float*)d_in[3];
    const float* Wk    = (const float*)d_in[4];
    const float* bk    = (const float*)d_in[5];
    const float* Wv    = (const float*)d_in[6];
    const float* bv    = (const float*)d_in[7];
    const float* Wo    = (const float*)d_in[8];
    const float* bo    = (const float*)d_in[9];
    const float* rfreq = (const float*)d_in[10];
    float* out = (float*)d_out;

    __nv_bfloat16 *xh, *xm, *wh, *wm;
    cudaGetSymbolAddress((void**)&xh, g_xh);
    cudaGetSymbolAddress((void**)&xm, g_xm);
    cudaGetSymbolAddress((void**)&wh, g_wh);
    cudaGetSymbolAddress((void**)&wm, g_wm);

    cudaFuncSetAttribute(mega_kernel,
                         cudaFuncAttributeMaxDynamicSharedMemorySize, DSM_BYTES);

    // 1) Split x and weights into bf16 hi/mid + reset dataflow counters
    int nblk = XN / 1024 + 4 * WN / 1024;     // 1344
    split_kernel<<<nblk, 256>>>(x, Wq, Wk, Wv, Wo, xh, xm, wh, wm);

    // 2) Fused QKV + attention + O-projection, bid-ordered dataflow
    mega_kernel<<<960, 256, DSM_BYTES>>>(pos, rfreq, bq, bk, bv, bo, out);
}

// round 13
// speedup vs baseline: 1.4785x; 1.3004x over previous
#include <cuda_runtime.h>
#include <cuda_fp16.h>
#include <mma.h>
#include <cstdint>

using namespace nvcuda;

// Problem constants (fixed by the reference)
#define NTOT   2048
#define NGR    32
#define NPG    64
#define C      384
#define G12    12
#define HEFF   2
#define GH     24
#define HD     16

#define XN (NTOT * C)        // 786432
#define WN (C * C)           // 147456

// Scratch (device globals — no allocation allowed)
__device__ float g_q[XN];
__device__ float g_k[XN];
__device__ float g_v[XN];
__device__ __half g_xh[XN];              // x hi
__device__ __half g_xm[XN];              // x mid (residual)
__device__ __half g_wh[4 * WN];          // Wq | Wk | Wv | Wo hi (B operand: hi only)
__device__ __half g_ah[XN];              // attention output hi
__device__ __half g_am[XN];              // attention output mid
__device__ int g_c1[NGR];                // QKV-done counters (18 per graph)
__device__ int g_c2[NGR];                // attn-done counters (6 per graph)

// ---------------------------------------------------------------------------
// cp.async helpers
// ---------------------------------------------------------------------------
__device__ __forceinline__ void cp16(unsigned int dst, const void* src) {
    asm volatile("cp.async.cg.shared.global [%0], [%1], 16;\n" :: "r"(dst), "l"(src));
}
__device__ __forceinline__ void cp_commit() {
    asm volatile("cp.async.commit_group;\n");
}
template <int N>
__device__ __forceinline__ void cp_wait() {
    asm volatile("cp.async.wait_group %0;\n" :: "n"(N));
}

// ---------------------------------------------------------------------------
// One-shot split: x -> fp16 hi+mid; weights -> fp16 hi only.
// Block 0 also resets the dataflow counters (kernel completes before mega).
// ---------------------------------------------------------------------------
__global__ __launch_bounds__(256) void split_kernel(
    const float* __restrict__ x,
    const float* __restrict__ wq, const float* __restrict__ wk,
    const float* __restrict__ wv, const float* __restrict__ wo,
    __half* __restrict__ xh, __half* __restrict__ xm,
    __half* __restrict__ wh)
{
    const int bid = blockIdx.x;
    if (bid == 0 && threadIdx.x < 2 * NGR) {
        if (threadIdx.x < NGR) g_c1[threadIdx.x] = 0;
        else                   g_c2[threadIdx.x - NGR] = 0;
    }
    if (bid < XN / 1024) {
        int loc = (bid * 256 + threadIdx.x) * 4;
        float4 v4 = *reinterpret_cast<const float4*>(&x[loc]);
        float v[4] = {v4.x, v4.y, v4.z, v4.w};
        __half h[4], m_[4];
        #pragma unroll
        for (int e = 0; e < 4; e++) {
            h[e]  = __float2half(v[e]);
            m_[e] = __float2half(v[e] - __half2float(h[e]));
        }
        __half2 hp0(h[0], h[1]), hp1(h[2], h[3]);
        __half2 mp0(m_[0], m_[1]), mp1(m_[2], m_[3]);
        *reinterpret_cast<uint2*>(&xh[loc]) = make_uint2(
            *reinterpret_cast<unsigned*>(&hp0), *reinterpret_cast<unsigned*>(&hp1));
        *reinterpret_cast<uint2*>(&xm[loc]) = make_uint2(
            *reinterpret_cast<unsigned*>(&mp0), *reinterpret_cast<unsigned*>(&mp1));
    } else {
        int w = ((bid - XN / 1024) * 256 + threadIdx.x) * 4;   // [0, 4*WN)
        int m = w / WN;
        int loc = w - m * WN;
        const float* src = (m == 0) ? wq : (m == 1) ? wk : (m == 2) ? wv : wo;
        float4 v4 = *reinterpret_cast<const float4*>(&src[loc]);
        __half2 hp0(__float2half(v4.x), __float2half(v4.y));
        __half2 hp1(__float2half(v4.z), __float2half(v4.w));
        *reinterpret_cast<uint2*>(&wh[m * WN + loc]) = make_uint2(
            *reinterpret_cast<unsigned*>(&hp0), *reinterpret_cast<unsigned*>(&hp1));
    }
}

// ---------------------------------------------------------------------------
// GEMM tile (in-CTA split-K over 8 warps, fp16 2-product):
//   O[br*64:+64, bc*64:+64] = (Ah+Am) @ Bh + bias. 256 threads, BK=64/iter,
//   2-stage cp.async ring. acc += ah*bh; acc += am*bh (A fp32-exact in fp16x2).
// ---------------------------------------------------------------------------
#define TST 72                       // smem tile row stride (elems) = 144B
#define AH_O 0
#define AM_O 9216                    // 64*144
#define BH_O 18432
#define STG_BYTES 27648              // 3 tiles * 9216
#define DSM_BYTES (2 * STG_BYTES)    // 55296

__device__ __forceinline__ void gemm_tile(
    unsigned char* dsm,
    const __half* __restrict__ Ah, const __half* __restrict__ Am,
    const __half* __restrict__ Bh,
    const float* __restrict__ bias, float* __restrict__ O,
    int br, int bc, int K, int N)
{
    const unsigned int sbase = (unsigned int)__cvta_generic_to_shared(dsm);
    const int tid  = threadIdx.x;
    const int warp = tid >> 5;
    const int kg   = warp >> 2;
    const int wr   = (warp >> 1) & 1;
    const int wc   = warp & 1;
    const int niter = K >> 6;

    const int r0 = tid >> 3,           c0 = (tid & 7) * 16;
    const int r1 = (tid + 256) >> 3,   c1 = ((tid + 256) & 7) * 16;

    const __half* agh0 = Ah + (long)(br * 64 + r0) * K + (c0 >> 1);
    const __half* agh1 = Ah + (long)(br * 64 + r1) * K + (c1 >> 1);
    const __half* agm0 = Am + (long)(br * 64 + r0) * K + (c0 >> 1);
    const __half* agm1 = Am + (long)(br * 64 + r1) * K + (c1 >> 1);
    const __half* bgh0 = Bh + (long)r0 * N + bc * 64 + (c0 >> 1);
    const __half* bgh1 = Bh + (long)r1 * N + bc * 64 + (c1 >> 1);

    const unsigned int sa0 = r0 * (TST * 2) + c0;
    const unsigned int sa1 = r1 * (TST * 2) + c1;

    auto load_stage = [&](int stg, int it) {
        const unsigned sb = sbase + stg * STG_BYTES;
        const int ko = it * 64;
        const long bko = (long)it * 64 * N;
        cp16(sb + AH_O + sa0, agh0 + ko);
        cp16(sb + AH_O + sa1, agh1 + ko);
        cp16(sb + AM_O + sa0, agm0 + ko);
        cp16(sb + AM_O + sa1, agm1 + ko);
        cp16(sb + BH_O + sa0, bgh0 + bko);
        cp16(sb + BH_O + sa1, bgh1 + bko);
        cp_commit();
    };

    load_stage(0, 0);
    if (niter > 1) load_stage(1, 1);

    wmma::fragment<wmma::accumulator, 16, 16, 16, float> acc[2][2];
    #pragma unroll
    for (int i = 0; i < 2; i++)
        #pragma unroll
        for (int j = 0; j < 2; j++)
            wmma::fill_fragment(acc[i][j], 0.0f);

    for (int it = 0; it < niter; it++) {
        const int s = it & 1;
        if (it + 1 < niter) { cp_wait<1>(); } else { cp_wait<0>(); }
        __syncthreads();

        const __half* ash  = reinterpret_cast<const __half*>(dsm + s * STG_BYTES + AH_O);
        const __half* asm_ = reinterpret_cast<const __half*>(dsm + s * STG_BYTES + AM_O);
        const __half* bsh  = reinterpret_cast<const __half*>(dsm + s * STG_BYTES + BH_O);

        #pragma unroll
        for (int ks = 0; ks < 2; ks++) {
            const int k16 = kg * 32 + ks * 16;
            wmma::fragment<wmma::matrix_a, 16, 16, 16, __half, wmma::row_major> ah[2], am[2];
            wmma::fragment<wmma::matrix_b, 16, 16, 16, __half, wmma::row_major> bh[2];
            #pragma unroll
            for (int i = 0; i < 2; i++) {
                wmma::load_matrix_sync(ah[i], ash + (wr * 32 + i * 16) * TST + k16, TST);
                wmma::load_matrix_sync(am[i], asm_ + (wr * 32 + i * 16) * TST + k16, TST);
            }
            #pragma unroll
            for (int j = 0; j < 2; j++)
                wmma::load_matrix_sync(bh[j], bsh + k16 * TST + wc * 32 + j * 16, TST);
            #pragma unroll
            for (int i = 0; i < 2; i++)
                #pragma unroll
                for (int j = 0; j < 2; j++)
                    wmma::mma_sync(acc[i][j], ah[i], bh[j], acc[i][j]);
            #pragma unroll
            for (int i = 0; i < 2; i++)
                #pragma unroll
                for (int j = 0; j < 2; j++)
                    wmma::mma_sync(acc[i][j], am[i], bh[j], acc[i][j]);
        }
        __syncthreads();
        if (it + 2 < niter) load_stage(s, it + 2);
    }

    float (*Cs0)[64] = reinterpret_cast<float(*)[64]>(dsm);
    float (*Cs1)[64] = reinterpret_cast<float(*)[64]>(dsm + 16384);
    float (*Cbuf)[64] = (kg == 0) ? Cs0 : Cs1;
    #pragma unroll
    for (int i = 0; i < 2; i++)
        #pragma unroll
        for (int j = 0; j < 2; j++)
            wmma::store_matrix_sync(&Cbuf[wr * 32 + i * 16][wc * 32 + j * 16],
                                    acc[i][j], 64, wmma::mem_row_major);
    __syncthreads();

    #pragma unroll
    for (int l = 0; l < 16; l++) {
        int idx = tid + l * 256;
        int r = idx >> 6, c = idx & 63;
        O[(long)(br * 64 + r) * N + bc * 64 + c] =
            Cs0[r][c] + Cs1[r][c] + bias[bc * 64 + c];
    }
}

// ---------------------------------------------------------------------------
// Mega kernel: QKV GEMM (bids 0..575) -> attention (576..767) -> O GEMM
// (768..959), one launch. Per-graph atomic counters; bid-ordered dispatch.
// ---------------------------------------------------------------------------
__global__ __launch_bounds__(256, 2) void mega_kernel(
    const float* __restrict__ pos, const float* __restrict__ freqs,
    const float* __restrict__ bq, const float* __restrict__ bk,
    const float* __restrict__ bv, const float* __restrict__ bo,
    float* __restrict__ out)
{
    extern __shared__ __align__(16) unsigned char dsm[];
    const int bid = blockIdx.x;
    const int tid = threadIdx.x;

    if (bid < 576) {
        // ---- QKV projection: 18 CTAs per graph/row-tile ----
        const int g     = bid / 18;
        const int rem   = bid % 18;
        const int which = rem / 6;
        const int bc    = rem % 6;
        const __half* Bh = g_wh + (long)which * WN;
        const float* bias = (which == 0) ? bq : (which == 1) ? bk : bv;
        float* O = (which == 0) ? g_q : (which == 1) ? g_k : g_v;
        gemm_tile(dsm, g_xh, g_xm, Bh, bias, O, g, bc, C, C);
        __threadfence();
        __syncthreads();
        if (tid == 0) atomicAdd(&g_c1[g], 1);

    } else if (bid < 768) {
        // ---- Attention (RoPE fused), 6 CTAs per graph, 4 gh each ----
        const int a     = bid - 576;
        const int graph = a / 6;
        const int blk   = a % 6;
        const int sub   = tid >> 6;
        const int i     = tid & 63;
        const int gh    = blk * 4 + sub;
        const int h     = gh & 1;

        if (tid == 0) {
            while (atomicAdd(&g_c1[graph], 0) < 18) __nanosleep(64);
        }
        __syncthreads();
        __threadfence();

        float (*Ks)[64][16] = reinterpret_cast<float(*)[64][16]>(dsm);
        float (*Vs)[64][16] = reinterpret_cast<float(*)[64][16]>(dsm + 16384);

        const int node = graph * NPG + i;
        const int off  = node * C + gh * HD;

        float qr[16], kr[16];
        {
            const float4* qp = reinterpret_cast<const float4*>(g_q + off);
            const float4* kp = reinterpret_cast<const float4*>(g_k + off);
            const float4* vp = reinterpret_cast<const float4*>(g_v + off);
            float4* vs = reinterpret_cast<float4*>(&Vs[sub][i][0]);
            #pragma unroll
            for (int t = 0; t < 4; t++) {
                float4 qv = qp[t];
                qr[4*t+0] = qv.x; qr[4*t+1] = qv.y; qr[4*t+2] = qv.z; qr[4*t+3] = qv.w;
                float4 kv = kp[t];
                kr[4*t+0] = kv.x; kr[4*t+1] = kv.y; kr[4*t+2] = kv.z; kr[4*t+3] = kv.w;
                vs[t] = vp[t];
            }
        }

        const float p0 = pos[node * 3 + 0];
        const float p1 = pos[node * 3 + 1];
        const float p2 = pos[node * 3 + 2];
        #pragma unroll
        for (int f = 0; f < 8; f++) {
            float th = p0 * freqs[ 0 + h * 8 + f]
                     + p1 * freqs[16 + h * 8 + f]
                     + p2 * freqs[32 + h * 8 + f];
            float s, c;
            __sincosf(th, &s, &c);
            float q1 = qr[2*f], q2 = qr[2*f+1];
            qr[2*f]   = q1 * c - q2 * s;
            qr[2*f+1] = q1 * s + q2 * c;
            float k1 = kr[2*f], k2 = kr[2*f+1];
            kr[2*f]   = k1 * c - k2 * s;
            kr[2*f+1] = k1 * s + k2 * c;
        }
        #pragma unroll
        for (int d = 0; d < 16; d++) qr[d] *= 0.25f;
        #pragma unroll
        for (int d = 0; d < 16; d++) Ks[sub][i][d] = kr[d];
        __syncthreads();

        float den = 0.f;
        float o[16] = {};
        #pragma unroll 2
        for (int j = 0; j < 64; j++) {
            float s = 0.f;
            #pragma unroll
            for (int d = 0; d < 16; d++) s = fmaf(qr[d], Ks[sub][j][d], s);
            float e = __expf(s);
            den += e;
            #pragma unroll
            for (int d = 0; d < 16; d++) o[d] = fmaf(e, Vs[sub][j][d], o[d]);
        }
        float inv = 1.f / den;

        __half hb[16], mb[16];
        #pragma unroll
        for (int d = 0; d < 16; d++) {
            float val = o[d] * inv;
            hb[d] = __float2half(val);
            mb[d] = __float2half(val - __half2float(hb[d]));
        }
        uint4 uh0, uh1, um0, um1;
        unsigned* uhp0 = &uh0.x; unsigned* uhp1 = &uh1.x;
        unsigned* ump0 = &um0.x; unsigned* ump1 = &um1.x;
        #pragma unroll
        for (int t = 0; t < 4; t++) {
            __half2 a2(hb[2*t], hb[2*t+1]);      uhp0[t] = *reinterpret_cast<unsigned*>(&a2);
            __half2 b2(hb[8+2*t], hb[8+2*t+1]);  uhp1[t] = *reinterpret_cast<unsigned*>(&b2);
            __half2 c2(mb[2*t], mb[2*t+1]);      ump0[t] = *reinterpret_cast<unsigned*>(&c2);
            __half2 d2(mb[8+2*t], mb[8+2*t+1]);  ump1[t] = *reinterpret_cast<unsigned*>(&d2);
        }
        uint4* ahp = reinterpret_cast<uint4*>(&g_ah[off]);
        uint4* amp = reinterpret_cast<uint4*>(&g_am[off]);
        ahp[0] = uh0; ahp[1] = uh1;
        amp[0] = um0; amp[1] = um1;

        __threadfence();
        __syncthreads();
        if (tid == 0) atomicAdd(&g_c2[graph], 1);

    } else {
        // ---- Output projection: row-tile = graph, 6 CTAs per graph ----
        const int o  = bid - 768;
        const int br = o / 6;
        const int bc = o % 6;

        if (tid == 0) {
            while (atomicAdd(&g_c2[br], 0) < 6) __nanosleep(64);
        }
        __syncthreads();
        __threadfence();

        gemm_tile(dsm, g_ah, g_am, g_wh + 3L * WN, bo, out, br, bc, C, C);
    }
}

// ---------------------------------------------------------------------------
extern "C" void kernel_launch(void* const* d_in, const int* in_sizes, int n_in,
                              void* d_out, int out_size)
{
    const float* x     = (const float*)d_in[0];
    const float* pos   = (const float*)d_in[1];
    const float* Wq    = (const float*)d_in[2];
    const float* bq    = (const float*)d_in[3];
    const float* Wk    = (const float*)d_in[4];
    const float* bk    = (const float*)d_in[5];
    const float* Wv    = (const float*)d_in[6];
    const float* bv    = (const float*)d_in[7];
    const float* Wo    = (const float*)d_in[8];
    const float* bo    = (const float*)d_in[9];
    const float* rfreq = (const float*)d_in[10];
    float* out = (float*)d_out;

    __half *xh, *xm, *wh;
    cudaGetSymbolAddress((void**)&xh, g_xh);
    cudaGetSymbolAddress((void**)&xm, g_xm);
    cudaGetSymbolAddress((void**)&wh, g_wh);

    cudaFuncSetAttribute(mega_kernel,
                         cudaFuncAttributeMaxDynamicSharedMemorySize, DSM_BYTES);

    // 1) Split x (hi+mid) and weights (hi) + reset dataflow counters
    int nblk = XN / 1024 + 4 * WN / 1024;     // 1344
    split_kernel<<<nblk, 256>>>(x, Wq, Wk, Wv, Wo, xh, xm, wh);

    // 2) Fused QKV + attention + O-projection, bid-ordered dataflow
    mega_kernel<<<960, 256, DSM_BYTES>>>(pos, rfreq, bq, bk, bv, bo, out);
}

// round 14
// speedup vs baseline: 1.5374x; 1.0398x over previous
#include <cuda_runtime.h>
#include <cuda_fp16.h>
#include <mma.h>
#include <cstdint>

using namespace nvcuda;

// Problem constants (fixed by the reference)
#define NTOT   2048
#define NGR    32
#define NPG    64
#define C      384
#define G12    12
#define HEFF   2
#define GH     24
#define HD     16

#define XN (NTOT * C)        // 786432
#define WN (C * C)           // 147456

// Scratch (device globals — no allocation allowed)
__device__ float g_q[XN];
__device__ float g_k[XN];
__device__ float g_v[XN];
__device__ __half g_xh[XN];              // x hi
__device__ __half g_xm[XN];              // x mid (residual)
__device__ __half g_wh[4 * WN];          // Wq | Wk | Wv | Wo hi (B operand)
__device__ __half g_ah[XN];              // attention output hi
__device__ __half g_am[XN];              // attention output mid
__device__ int g_c1[NGR];                // QKV-done counters (18 per graph)
__device__ int g_c2[NGR];                // attn-done counters (12 per graph)

// ---------------------------------------------------------------------------
// cp.async helpers
// ---------------------------------------------------------------------------
__device__ __forceinline__ void cp16(unsigned int dst, const void* src) {
    asm volatile("cp.async.cg.shared.global [%0], [%1], 16;\n" :: "r"(dst), "l"(src));
}
__device__ __forceinline__ void cp_commit() {
    asm volatile("cp.async.commit_group;\n");
}
template <int N>
__device__ __forceinline__ void cp_wait() {
    asm volatile("cp.async.wait_group %0;\n" :: "n"(N));
}

// ---------------------------------------------------------------------------
// One-shot split: x -> fp16 hi+mid; weights -> fp16 hi only.
// Block 0 also resets the dataflow counters.
// ---------------------------------------------------------------------------
__global__ __launch_bounds__(256) void split_kernel(
    const float* __restrict__ x,
    const float* __restrict__ wq, const float* __restrict__ wk,
    const float* __restrict__ wv, const float* __restrict__ wo,
    __half* __restrict__ xh, __half* __restrict__ xm,
    __half* __restrict__ wh)
{
    const int bid = blockIdx.x;
    if (bid == 0 && threadIdx.x < 2 * NGR) {
        if (threadIdx.x < NGR) g_c1[threadIdx.x] = 0;
        else                   g_c2[threadIdx.x - NGR] = 0;
    }
    if (bid < XN / 1024) {
        int loc = (bid * 256 + threadIdx.x) * 4;
        float4 v4 = *reinterpret_cast<const float4*>(&x[loc]);
        float v[4] = {v4.x, v4.y, v4.z, v4.w};
        __half h[4], m_[4];
        #pragma unroll
        for (int e = 0; e < 4; e++) {
            h[e]  = __float2half(v[e]);
            m_[e] = __float2half(v[e] - __half2float(h[e]));
        }
        __half2 hp0(h[0], h[1]), hp1(h[2], h[3]);
        __half2 mp0(m_[0], m_[1]), mp1(m_[2], m_[3]);
        *reinterpret_cast<uint2*>(&xh[loc]) = make_uint2(
            *reinterpret_cast<unsigned*>(&hp0), *reinterpret_cast<unsigned*>(&hp1));
        *reinterpret_cast<uint2*>(&xm[loc]) = make_uint2(
            *reinterpret_cast<unsigned*>(&mp0), *reinterpret_cast<unsigned*>(&mp1));
    } else {
        int w = ((bid - XN / 1024) * 256 + threadIdx.x) * 4;   // [0, 4*WN)
        int m = w / WN;
        int loc = w - m * WN;
        const float* src = (m == 0) ? wq : (m == 1) ? wk : (m == 2) ? wv : wo;
        float4 v4 = *reinterpret_cast<const float4*>(&src[loc]);
        __half2 hp0(__float2half(v4.x), __float2half(v4.y));
        __half2 hp1(__float2half(v4.z), __float2half(v4.w));
        *reinterpret_cast<uint2*>(&wh[m * WN + loc]) = make_uint2(
            *reinterpret_cast<unsigned*>(&hp0), *reinterpret_cast<unsigned*>(&hp1));
    }
}

// ---------------------------------------------------------------------------
// GEMM tile, fp16 2-product, 128 threads = 4 warps (2x2 of 32x32):
//   O[br*64:+64, bc*64:+64] = (Ah+Am) @ Bh + bias
// BK=32 per iter, 3-stage cp.async ring (deep pipeline).
// ---------------------------------------------------------------------------
#define ASTR 40                      // A smem row stride (elems) = 80B
#define BSTR 72                      // B smem row stride (elems) = 144B
#define AH_O 0
#define AM_O 5120                    // 64*80
#define BH_O 10240                   // + 64*80
#define STG_BYTES 14848              // + 32*144
#define DSM_BYTES (3 * STG_BYTES)    // 44544

__device__ __forceinline__ void gemm_tile(
    unsigned char* dsm,
    const __half* __restrict__ Ah, const __half* __restrict__ Am,
    const __half* __restrict__ Bh,
    const float* __restrict__ bias, float* __restrict__ O,
    int br, int bc, int K, int N)
{
    const unsigned int sbase = (unsigned int)__cvta_generic_to_shared(dsm);
    const int tid  = threadIdx.x;
    const int warp = tid >> 5;
    const int wr   = warp >> 1;
    const int wc   = warp & 1;
    const int niter = K >> 5;          // 12 for K=384

    // A tile 64x32 fp16 (64B data/row): 256 16B-segs, 2/thread. r=s>>2,c=s&3.
    const int ar0 = tid >> 2,           ac0 = (tid & 3) * 16;
    const int ar1 = (tid + 128) >> 2,   ac1 = ((tid + 128) & 3) * 16;
    // B tile 32x64 fp16 (128B data/row): 256 segs, 2/thread. r=s>>3,c=s&7.
    const int br0 = tid >> 3,           bc0 = (tid & 7) * 16;
    const int br1 = (tid + 128) >> 3,   bc1 = ((tid + 128) & 7) * 16;

    const __half* agh0 = Ah + (long)(br * 64 + ar0) * K + (ac0 >> 1);
    const __half* agh1 = Ah + (long)(br * 64 + ar1) * K + (ac1 >> 1);
    const __half* agm0 = Am + (long)(br * 64 + ar0) * K + (ac0 >> 1);
    const __half* agm1 = Am + (long)(br * 64 + ar1) * K + (ac1 >> 1);
    const __half* bgh0 = Bh + (long)br0 * N + bc * 64 + (bc0 >> 1);
    const __half* bgh1 = Bh + (long)br1 * N + bc * 64 + (bc1 >> 1);

    const unsigned int saa0 = ar0 * (ASTR * 2) + ac0;
    const unsigned int saa1 = ar1 * (ASTR * 2) + ac1;
    const unsigned int sab0 = br0 * (BSTR * 2) + bc0;
    const unsigned int sab1 = br1 * (BSTR * 2) + bc1;

    auto load_stage = [&](int stg, int it) {
        const unsigned sb = sbase + stg * STG_BYTES;
        const int ko = it * 32;
        const long bko = (long)it * 32 * N;
        cp16(sb + AH_O + saa0, agh0 + ko);
        cp16(sb + AH_O + saa1, agh1 + ko);
        cp16(sb + AM_O + saa0, agm0 + ko);
        cp16(sb + AM_O + saa1, agm1 + ko);
        cp16(sb + BH_O + sab0, bgh0 + bko);
        cp16(sb + BH_O + sab1, bgh1 + bko);
        cp_commit();
    };

    load_stage(0, 0);
    load_stage(1, 1);

    wmma::fragment<wmma::accumulator, 16, 16, 16, float> acc[2][2];
    #pragma unroll
    for (int i = 0; i < 2; i++)
        #pragma unroll
        for (int j = 0; j < 2; j++)
            wmma::fill_fragment(acc[i][j], 0.0f);

    for (int it = 0; it < niter; it++) {
        const int s = it % 3;
        if (it + 2 < niter) {
            load_stage((it + 2) % 3, it + 2);
            cp_wait<2>();
        } else if (it + 1 < niter) {
            cp_wait<1>();
        } else {
            cp_wait<0>();
        }
        __syncthreads();

        const __half* ash  = reinterpret_cast<const __half*>(dsm + s * STG_BYTES + AH_O);
        const __half* asm_ = reinterpret_cast<const __half*>(dsm + s * STG_BYTES + AM_O);
        const __half* bsh  = reinterpret_cast<const __half*>(dsm + s * STG_BYTES + BH_O);

        #pragma unroll
        for (int ks = 0; ks < 2; ks++) {
            const int k16 = ks * 16;
            wmma::fragment<wmma::matrix_a, 16, 16, 16, __half, wmma::row_major> ah[2], am[2];
            wmma::fragment<wmma::matrix_b, 16, 16, 16, __half, wmma::row_major> bh[2];
            #pragma unroll
            for (int i = 0; i < 2; i++) {
                wmma::load_matrix_sync(ah[i], ash + (wr * 32 + i * 16) * ASTR + k16, ASTR);
                wmma::load_matrix_sync(am[i], asm_ + (wr * 32 + i * 16) * ASTR + k16, ASTR);
            }
            #pragma unroll
            for (int j = 0; j < 2; j++)
                wmma::load_matrix_sync(bh[j], bsh + k16 * BSTR + wc * 32 + j * 16, BSTR);
            #pragma unroll
            for (int i = 0; i < 2; i++)
                #pragma unroll
                for (int j = 0; j < 2; j++)
                    wmma::mma_sync(acc[i][j], ah[i], bh[j], acc[i][j]);
            #pragma unroll
            for (int i = 0; i < 2; i++)
                #pragma unroll
                for (int j = 0; j < 2; j++)
                    wmma::mma_sync(acc[i][j], am[i], bh[j], acc[i][j]);
        }
        __syncthreads();
    }

    // Epilogue: acc -> aliased fp32 smem -> global (+bias), coalesced
    float (*Cs)[64] = reinterpret_cast<float(*)[64]>(dsm);
    #pragma unroll
    for (int i = 0; i < 2; i++)
        #pragma unroll
        for (int j = 0; j < 2; j++)
            wmma::store_matrix_sync(&Cs[wr * 32 + i * 16][wc * 32 + j * 16],
                                    acc[i][j], 64, wmma::mem_row_major);
    __syncthreads();

    #pragma unroll
    for (int l = 0; l < 32; l++) {
        int idx = tid + l * 128;
        int r = idx >> 6, c = idx & 63;
        O[(long)(br * 64 + r) * N + bc * 64 + c] = Cs[r][c] + bias[bc * 64 + c];
    }
}

// ---------------------------------------------------------------------------
// Mega kernel (128 threads/CTA): QKV GEMM (bids 0..575) -> attention
// (576..959, 2 gh-slices per CTA) -> O GEMM (960..1151), one launch.
// Per-graph atomic counters; bid-ordered dispatch (producers first).
// ---------------------------------------------------------------------------
__global__ __launch_bounds__(128, 4) void mega_kernel(
    const float* __restrict__ pos, const float* __restrict__ freqs,
    const float* __restrict__ bq, const float* __restrict__ bk,
    const float* __restrict__ bv, const float* __restrict__ bo,
    float* __restrict__ out)
{
    extern __shared__ __align__(16) unsigned char dsm[];
    const int bid = blockIdx.x;
    const int tid = threadIdx.x;

    if (bid < 576) {
        // ---- QKV projection: 18 CTAs per graph/row-tile ----
        const int g     = bid / 18;
        const int rem   = bid % 18;
        const int which = rem / 6;
        const int bc    = rem % 6;
        const __half* Bh = g_wh + (long)which * WN;
        const float* bias = (which == 0) ? bq : (which == 1) ? bk : bv;
        float* O = (which == 0) ? g_q : (which == 1) ? g_k : g_v;
        gemm_tile(dsm, g_xh, g_xm, Bh, bias, O, g, bc, C, C);
        __threadfence();
        __syncthreads();
        if (tid == 0) atomicAdd(&g_c1[g], 1);

    } else if (bid < 960) {
        // ---- Attention (RoPE fused), 12 CTAs per graph, 2 gh each ----
        const int a     = bid - 576;
        const int graph = a / 12;
        const int blk   = a % 12;
        const int sub   = tid >> 6;        // 0..1
        const int i     = tid & 63;
        const int gh    = blk * 2 + sub;
        const int h     = gh & 1;

        if (tid == 0) {
            while (atomicAdd(&g_c1[graph], 0) < 18) __nanosleep(64);
        }
        __syncthreads();
        __threadfence();

        float (*Ks)[64][16] = reinterpret_cast<float(*)[64][16]>(dsm);
        float (*Vs)[64][16] = reinterpret_cast<float(*)[64][16]>(dsm + 8192);

        const int node = graph * NPG + i;
        const int off  = node * C + gh * HD;

        float qr[16], kr[16];
        {
            const float4* qp = reinterpret_cast<const float4*>(g_q + off);
            const float4* kp = reinterpret_cast<const float4*>(g_k + off);
            const float4* vp = reinterpret_cast<const float4*>(g_v + off);
            float4* vs = reinterpret_cast<float4*>(&Vs[sub][i][0]);
            #pragma unroll
            for (int t = 0; t < 4; t++) {
                float4 qv = qp[t];
                qr[4*t+0] = qv.x; qr[4*t+1] = qv.y; qr[4*t+2] = qv.z; qr[4*t+3] = qv.w;
                float4 kv = kp[t];
                kr[4*t+0] = kv.x; kr[4*t+1] = kv.y; kr[4*t+2] = kv.z; kr[4*t+3] = kv.w;
                vs[t] = vp[t];
            }
        }

        const float p0 = pos[node * 3 + 0];
        const float p1 = pos[node * 3 + 1];
        const float p2 = pos[node * 3 + 2];
        #pragma unroll
        for (int f = 0; f < 8; f++) {
            float th = p0 * freqs[ 0 + h * 8 + f]
                     + p1 * freqs[16 + h * 8 + f]
                     + p2 * freqs[32 + h * 8 + f];
            float s, c;
            __sincosf(th, &s, &c);
            float q1 = qr[2*f], q2 = qr[2*f+1];
            qr[2*f]   = q1 * c - q2 * s;
            qr[2*f+1] = q1 * s + q2 * c;
            float k1 = kr[2*f], k2 = kr[2*f+1];
            kr[2*f]   = k1 * c - k2 * s;
            kr[2*f+1] = k1 * s + k2 * c;
        }
        #pragma unroll
        for (int d = 0; d < 16; d++) qr[d] *= 0.25f;
        #pragma unroll
        for (int d = 0; d < 16; d++) Ks[sub][i][d] = kr[d];
        __syncthreads();

        float den = 0.f;
        float o[16] = {};
        #pragma unroll 2
        for (int j = 0; j < 64; j++) {
            float s = 0.f;
            #pragma unroll
            for (int d = 0; d < 16; d++) s = fmaf(qr[d], Ks[sub][j][d], s);
            float e = __expf(s);
            den += e;
            #pragma unroll
            for (int d = 0; d < 16; d++) o[d] = fmaf(e, Vs[sub][j][d], o[d]);
        }
        float inv = 1.f / den;

        __half hb[16], mb[16];
        #pragma unroll
        for (int d = 0; d < 16; d++) {
            float val = o[d] * inv;
            hb[d] = __float2half(val);
            mb[d] = __float2half(val - __half2float(hb[d]));
        }
        uint4 uh0, uh1, um0, um1;
        unsigned* uhp0 = &uh0.x; unsigned* uhp1 = &uh1.x;
        unsigned* ump0 = &um0.x; unsigned* ump1 = &um1.x;
        #pragma unroll
        for (int t = 0; t < 4; t++) {
            __half2 a2(hb[2*t], hb[2*t+1]);      uhp0[t] = *reinterpret_cast<unsigned*>(&a2);
            __half2 b2(hb[8+2*t], hb[8+2*t+1]);  uhp1[t] = *reinterpret_cast<unsigned*>(&b2);
            __half2 c2(mb[2*t], mb[2*t+1]);      ump0[t] = *reinterpret_cast<unsigned*>(&c2);
            __half2 d2(mb[8+2*t], mb[8+2*t+1]);  ump1[t] = *reinterpret_cast<unsigned*>(&d2);
        }
        uint4* ahp = reinterpret_cast<uint4*>(&g_ah[off]);
        uint4* amp = reinterpret_cast<uint4*>(&g_am[off]);
        ahp[0] = uh0; ahp[1] = uh1;
        amp[0] = um0; amp[1] = um1;

        __threadfence();
        __syncthreads();
        if (tid == 0) atomicAdd(&g_c2[graph], 1);

    } else {
        // ---- Output projection: row-tile = graph, 6 CTAs per graph ----
        const int o  = bid - 960;
        const int br = o / 6;
        const int bc = o % 6;

        if (tid == 0) {
            while (atomicAdd(&g_c2[br], 0) < 12) __nanosleep(64);
        }
        __syncthreads();
        __threadfence();

        gemm_tile(dsm, g_ah, g_am, g_wh + 3L * WN, bo, out, br, bc, C, C);
    }
}

// ---------------------------------------------------------------------------
extern "C" void kernel_launch(void* const* d_in, const int* in_sizes, int n_in,
                              void* d_out, int out_size)
{
    const float* x     = (const float*)d_in[0];
    const float* pos   = (const float*)d_in[1];
    const float* Wq    = (const float*)d_in[2];
    const float* bq    = (const float*)d_in[3];
    const float* Wk    = (const float*)d_in[4];
    const float* bk    = (const float*)d_in[5];
    const float* Wv    = (const float*)d_in[6];
    const float* bv    = (const float*)d_in[7];
    const float* Wo    = (const float*)d_in[8];
    const float* bo    = (const float*)d_in[9];
    const float* rfreq = (const float*)d_in[10];
    float* out = (float*)d_out;

    __half *xh, *xm, *wh;
    cudaGetSymbolAddress((void**)&xh, g_xh);
    cudaGetSymbolAddress((void**)&xm, g_xm);
    cudaGetSymbolAddress((void**)&wh, g_wh);

    cudaFuncSetAttribute(mega_kernel,
                         cudaFuncAttributeMaxDynamicSharedMemorySize, DSM_BYTES);

    // 1) Split x (hi+mid) and weights (hi) + reset dataflow counters
    int nblk = XN / 1024 + 4 * WN / 1024;     // 1344
    split_kernel<<<nblk, 256>>>(x, Wq, Wk, Wv, Wo, xh, xm, wh);

    // 2) Fused QKV + attention + O-projection, bid-ordered dataflow
    mega_kernel<<<1152, 128, DSM_BYTES>>>(pos, rfreq, bq, bk, bv, bo, out);
}

// round 15
// speedup vs baseline: 1.6188x; 1.0530x over previous
#include <cuda_runtime.h>
#include <cuda_fp16.h>
#include <mma.h>
#include <cstdint>

using namespace nvcuda;

// Problem constants (fixed by the reference)
#define NTOT   2048
#define NGR    32
#define NPG    64
#define C      384
#define G12    12
#define HEFF   2
#define GH     24
#define HD     16

#define XN (NTOT * C)        // 786432
#define WN (C * C)           // 147456

// Scratch (device globals — no allocation allowed)
__device__ float g_q[XN];
__device__ float g_k[XN];
__device__ float g_v[XN];
__device__ __half g_xh[XN];              // x fp16
__device__ __half g_wh[4 * WN];          // Wq | Wk | Wv | Wo fp16
__device__ __half g_ah[XN];              // attention output fp16
__device__ int g_c1[NGR];                // QKV-done counters (18 per graph)
__device__ int g_c2[NGR];                // attn-done counters (12 per graph)

// ---------------------------------------------------------------------------
// cp.async helpers
// ---------------------------------------------------------------------------
__device__ __forceinline__ void cp16(unsigned int dst, const void* src) {
    asm volatile("cp.async.cg.shared.global [%0], [%1], 16;\n" :: "r"(dst), "l"(src));
}
__device__ __forceinline__ void cp_commit() {
    asm volatile("cp.async.commit_group;\n");
}
template <int N>
__device__ __forceinline__ void cp_wait() {
    asm volatile("cp.async.wait_group %0;\n" :: "n"(N));
}

// ---------------------------------------------------------------------------
// One-shot convert: x and the 4 weight matrices -> fp16.
// Block 0 also resets the dataflow counters.
// ---------------------------------------------------------------------------
__global__ __launch_bounds__(256) void split_kernel(
    const float* __restrict__ x,
    const float* __restrict__ wq, const float* __restrict__ wk,
    const float* __restrict__ wv, const float* __restrict__ wo,
    __half* __restrict__ xh, __half* __restrict__ wh)
{
    const int bid = blockIdx.x;
    if (bid == 0 && threadIdx.x < 2 * NGR) {
        if (threadIdx.x < NGR) g_c1[threadIdx.x] = 0;
        else                   g_c2[threadIdx.x - NGR] = 0;
    }
    const float* src;
    __half* dst;
    int loc;
    if (bid < XN / 1024) {
        loc = (bid * 256 + threadIdx.x) * 4;
        src = x; dst = xh;
    } else {
        int w = ((bid - XN / 1024) * 256 + threadIdx.x) * 4;   // [0, 4*WN)
        int m = w / WN;
        loc = w - m * WN;
        src = (m == 0) ? wq : (m == 1) ? wk : (m == 2) ? wv : wo;
        dst = wh + m * WN;
    }
    float4 v4 = *reinterpret_cast<const float4*>(&src[loc]);
    __half2 hp0(__float2half(v4.x), __float2half(v4.y));
    __half2 hp1(__float2half(v4.z), __float2half(v4.w));
    *reinterpret_cast<uint2*>(&dst[loc]) = make_uint2(
        *reinterpret_cast<unsigned*>(&hp0), *reinterpret_cast<unsigned*>(&hp1));
}

// ---------------------------------------------------------------------------
// GEMM tile, pure fp16, 128 threads = 4 warps (2x2 of 32x32):
//   O[br*64:+64, bc*64:+64] = A @ B + bias  (fp32 accumulate + out)
// BK=32 per iter, 3-stage cp.async ring (deep pipeline).
// ---------------------------------------------------------------------------
#define ASTR 40                      // A smem row stride (elems) = 80B
#define BSTR 72                      // B smem row stride (elems) = 144B
#define AH_O 0
#define BH_O 5120                    // 64*80
#define STG_BYTES 9728               // + 32*144
#define DSM_BYTES (3 * STG_BYTES)    // 29184

__device__ __forceinline__ void gemm_tile(
    unsigned char* dsm,
    const __half* __restrict__ Ah, const __half* __restrict__ Bh,
    const float* __restrict__ bias, float* __restrict__ O,
    int br, int bc, int K, int N)
{
    const unsigned int sbase = (unsigned int)__cvta_generic_to_shared(dsm);
    const int tid  = threadIdx.x;
    const int warp = tid >> 5;
    const int wr   = warp >> 1;
    const int wc   = warp & 1;
    const int niter = K >> 5;          // 12 for K=384

    // A tile 64x32 fp16 (64B/row): 256 16B-segs, 2/thread. r=s>>2, c=s&3.
    const int ar0 = tid >> 2,           ac0 = (tid & 3) * 16;
    const int ar1 = (tid + 128) >> 2,   ac1 = ((tid + 128) & 3) * 16;
    // B tile 32x64 fp16 (128B/row): 256 segs, 2/thread. r=s>>3, c=s&7.
    const int br0 = tid >> 3,           bc0 = (tid & 7) * 16;
    const int br1 = (tid + 128) >> 3,   bc1 = ((tid + 128) & 7) * 16;

    const __half* agh0 = Ah + (long)(br * 64 + ar0) * K + (ac0 >> 1);
    const __half* agh1 = Ah + (long)(br * 64 + ar1) * K + (ac1 >> 1);
    const __half* bgh0 = Bh + (long)br0 * N + bc * 64 + (bc0 >> 1);
    const __half* bgh1 = Bh + (long)br1 * N + bc * 64 + (bc1 >> 1);

    const unsigned int saa0 = ar0 * (ASTR * 2) + ac0;
    const unsigned int saa1 = ar1 * (ASTR * 2) + ac1;
    const unsigned int sab0 = br0 * (BSTR * 2) + bc0;
    const unsigned int sab1 = br1 * (BSTR * 2) + bc1;

    auto load_stage = [&](int stg, int it) {
        const unsigned sb = sbase + stg * STG_BYTES;
        const int ko = it * 32;
        const long bko = (long)it * 32 * N;
        cp16(sb + AH_O + saa0, agh0 + ko);
        cp16(sb + AH_O + saa1, agh1 + ko);
        cp16(sb + BH_O + sab0, bgh0 + bko);
        cp16(sb + BH_O + sab1, bgh1 + bko);
        cp_commit();
    };

    load_stage(0, 0);
    load_stage(1, 1);

    wmma::fragment<wmma::accumulator, 16, 16, 16, float> acc[2][2];
    #pragma unroll
    for (int i = 0; i < 2; i++)
        #pragma unroll
        for (int j = 0; j < 2; j++)
            wmma::fill_fragment(acc[i][j], 0.0f);

    for (int it = 0; it < niter; it++) {
        const int s = it % 3;
        if (it + 2 < niter) {
            load_stage((it + 2) % 3, it + 2);
            cp_wait<2>();
        } else if (it + 1 < niter) {
            cp_wait<1>();
        } else {
            cp_wait<0>();
        }
        __syncthreads();

        const __half* ash = reinterpret_cast<const __half*>(dsm + s * STG_BYTES + AH_O);
        const __half* bsh = reinterpret_cast<const __half*>(dsm + s * STG_BYTES + BH_O);

        #pragma unroll
        for (int ks = 0; ks < 2; ks++) {
            const int k16 = ks * 16;
            wmma::fragment<wmma::matrix_a, 16, 16, 16, __half, wmma::row_major> ah[2];
            wmma::fragment<wmma::matrix_b, 16, 16, 16, __half, wmma::row_major> bh[2];
            #pragma unroll
            for (int i = 0; i < 2; i++)
                wmma::load_matrix_sync(ah[i], ash + (wr * 32 + i * 16) * ASTR + k16, ASTR);
            #pragma unroll
            for (int j = 0; j < 2; j++)
                wmma::load_matrix_sync(bh[j], bsh + k16 * BSTR + wc * 32 + j * 16, BSTR);
            #pragma unroll
            for (int i = 0; i < 2; i++)
                #pragma unroll
                for (int j = 0; j < 2; j++)
                    wmma::mma_sync(acc[i][j], ah[i], bh[j], acc[i][j]);
        }
        __syncthreads();
    }

    // Epilogue: acc -> aliased fp32 smem -> global (+bias), coalesced
    float (*Cs)[64] = reinterpret_cast<float(*)[64]>(dsm);
    #pragma unroll
    for (int i = 0; i < 2; i++)
        #pragma unroll
        for (int j = 0; j < 2; j++)
            wmma::store_matrix_sync(&Cs[wr * 32 + i * 16][wc * 32 + j * 16],
                                    acc[i][j], 64, wmma::mem_row_major);
    __syncthreads();

    #pragma unroll
    for (int l = 0; l < 32; l++) {
        int idx = tid + l * 128;
        int r = idx >> 6, c = idx & 63;
        O[(long)(br * 64 + r) * N + bc * 64 + c] = Cs[r][c] + bias[bc * 64 + c];
    }
}

// ---------------------------------------------------------------------------
// Mega kernel (128 threads/CTA): QKV GEMM (bids 0..575) -> attention
// (576..959, 2 gh-slices per CTA) -> O GEMM (960..1151), one launch.
// Per-graph atomic counters; bid-ordered dispatch (producers first).
// ---------------------------------------------------------------------------
__global__ __launch_bounds__(128, 5) void mega_kernel(
    const float* __restrict__ pos, const float* __restrict__ freqs,
    const float* __restrict__ bq, const float* __restrict__ bk,
    const float* __restrict__ bv, const float* __restrict__ bo,
    float* __restrict__ out)
{
    extern __shared__ __align__(16) unsigned char dsm[];
    const int bid = blockIdx.x;
    const int tid = threadIdx.x;

    if (bid < 576) {
        // ---- QKV projection: 18 CTAs per graph/row-tile ----
        const int g     = bid / 18;
        const int rem   = bid % 18;
        const int which = rem / 6;
        const int bc    = rem % 6;
        const __half* Bh = g_wh + (long)which * WN;
        const float* bias = (which == 0) ? bq : (which == 1) ? bk : bv;
        float* O = (which == 0) ? g_q : (which == 1) ? g_k : g_v;
        gemm_tile(dsm, g_xh, Bh, bias, O, g, bc, C, C);
        __threadfence();
        __syncthreads();
        if (tid == 0) atomicAdd(&g_c1[g], 1);

    } else if (bid < 960) {
        // ---- Attention (RoPE fused), 12 CTAs per graph, 2 gh each ----
        const int a     = bid - 576;
        const int graph = a / 12;
        const int blk   = a % 12;
        const int sub   = tid >> 6;        // 0..1
        const int i     = tid & 63;
        const int gh    = blk * 2 + sub;
        const int h     = gh & 1;

        if (tid == 0) {
            while (atomicAdd(&g_c1[graph], 0) < 18) __nanosleep(64);
        }
        __syncthreads();
        __threadfence();

        float (*Ks)[64][16] = reinterpret_cast<float(*)[64][16]>(dsm);
        float (*Vs)[64][16] = reinterpret_cast<float(*)[64][16]>(dsm + 8192);

        const int node = graph * NPG + i;
        const int off  = node * C + gh * HD;

        float qr[16], kr[16];
        {
            const float4* qp = reinterpret_cast<const float4*>(g_q + off);
            const float4* kp = reinterpret_cast<const float4*>(g_k + off);
            const float4* vp = reinterpret_cast<const float4*>(g_v + off);
            float4* vs = reinterpret_cast<float4*>(&Vs[sub][i][0]);
            #pragma unroll
            for (int t = 0; t < 4; t++) {
                float4 qv = qp[t];
                qr[4*t+0] = qv.x; qr[4*t+1] = qv.y; qr[4*t+2] = qv.z; qr[4*t+3] = qv.w;
                float4 kv = kp[t];
                kr[4*t+0] = kv.x; kr[4*t+1] = kv.y; kr[4*t+2] = kv.z; kr[4*t+3] = kv.w;
                vs[t] = vp[t];
            }
        }

        const float p0 = pos[node * 3 + 0];
        const float p1 = pos[node * 3 + 1];
        const float p2 = pos[node * 3 + 2];
        #pragma unroll
        for (int f = 0; f < 8; f++) {
            float th = p0 * freqs[ 0 + h * 8 + f]
                     + p1 * freqs[16 + h * 8 + f]
                     + p2 * freqs[32 + h * 8 + f];
            float s, c;
            __sincosf(th, &s, &c);
            float q1 = qr[2*f], q2 = qr[2*f+1];
            qr[2*f]   = q1 * c - q2 * s;
            qr[2*f+1] = q1 * s + q2 * c;
            float k1 = kr[2*f], k2 = kr[2*f+1];
            kr[2*f]   = k1 * c - k2 * s;
            kr[2*f+1] = k1 * s + k2 * c;
        }
        #pragma unroll
        for (int d = 0; d < 16; d++) qr[d] *= 0.25f;
        #pragma unroll
        for (int d = 0; d < 16; d++) Ks[sub][i][d] = kr[d];
        __syncthreads();

        float den = 0.f;
        float o[16] = {};
        #pragma unroll 2
        for (int j = 0; j < 64; j++) {
            float s = 0.f;
            #pragma unroll
            for (int d = 0; d < 16; d++) s = fmaf(qr[d], Ks[sub][j][d], s);
            float e = __expf(s);
            den += e;
            #pragma unroll
            for (int d = 0; d < 16; d++) o[d] = fmaf(e, Vs[sub][j][d], o[d]);
        }
        float inv = 1.f / den;

        __half hb[16];
        #pragma unroll
        for (int d = 0; d < 16; d++) hb[d] = __float2half(o[d] * inv);
        uint4 uh0, uh1;
        unsigned* uhp0 = &uh0.x; unsigned* uhp1 = &uh1.x;
        #pragma unroll
        for (int t = 0; t < 4; t++) {
            __half2 a2(hb[2*t], hb[2*t+1]);      uhp0[t] = *reinterpret_cast<unsigned*>(&a2);
            __half2 b2(hb[8+2*t], hb[8+2*t+1]);  uhp1[t] = *reinterpret_cast<unsigned*>(&b2);
        }
        uint4* ahp = reinterpret_cast<uint4*>(&g_ah[off]);
        ahp[0] = uh0; ahp[1] = uh1;

        __threadfence();
        __syncthreads();
        if (tid == 0) atomicAdd(&g_c2[graph], 1);

    } else {
        // ---- Output projection: row-tile = graph, 6 CTAs per graph ----
        const int o  = bid - 960;
        const int br = o / 6;
        const int bc = o % 6;

        if (tid == 0) {
            while (atomicAdd(&g_c2[br], 0) < 12) __nanosleep(64);
        }
        __syncthreads();
        __threadfence();

        gemm_tile(dsm, g_ah, g_wh + 3L * WN, bo, out, br, bc, C, C);
    }
}

// ---------------------------------------------------------------------------
extern "C" void kernel_launch(void* const* d_in, const int* in_sizes, int n_in,
                              void* d_out, int out_size)
{
    const float* x     = (const float*)d_in[0];
    const float* pos   = (const float*)d_in[1];
    const float* Wq    = (const float*)d_in[2];
    const float* bq    = (const float*)d_in[3];
    const float* Wk    = (const float*)d_in[4];
    const float* bk    = (const float*)d_in[5];
    const float* Wv    = (const float*)d_in[6];
    const float* bv    = (const float*)d_in[7];
    const float* Wo    = (const float*)d_in[8];
    const float* bo    = (const float*)d_in[9];
    const float* rfreq = (const float*)d_in[10];
    float* out = (float*)d_out;

    __half *xh, *wh;
    cudaGetSymbolAddress((void**)&xh, g_xh);
    cudaGetSymbolAddress((void**)&wh, g_wh);

    cudaFuncSetAttribute(mega_kernel,
                         cudaFuncAttributeMaxDynamicSharedMemorySize, DSM_BYTES);

    // 1) Convert x and weights to fp16 + reset dataflow counters
    int nblk = XN / 1024 + 4 * WN / 1024;     // 1344
    split_kernel<<<nblk, 256>>>(x, Wq, Wk, Wv, Wo, xh, wh);

    // 2) Fused QKV + attention + O-projection, bid-ordered dataflow
    mega_kernel<<<1152, 128, DSM_BYTES>>>(pos, rfreq, bq, bk, bv, bo, out);
}

// round 16
// speedup vs baseline: 1.8048x; 1.1148x over previous
#include <cuda_runtime.h>
#include <cuda_fp16.h>
#include <mma.h>
#include <cstdint>

using namespace nvcuda;

// Problem constants (fixed by the reference)
#define NTOT   2048
#define NGR    32
#define NPG    64
#define C      384
#define G12    12
#define HEFF   2
#define GH     24
#define HD     16

#define XN (NTOT * C)        // 786432
#define WN (C * C)           // 147456

// Scratch (device globals — no allocation allowed)
__device__ float g_q[XN];
__device__ float g_k[XN];
__device__ float g_v[XN];
__device__ __half g_xh[XN];              // x fp16
__device__ __half g_wh[4 * WN];          // Wq | Wk | Wv | Wo fp16
__device__ __half g_ah[XN];              // attention output fp16
__device__ int g_c1[NGR];                // QKV-done counters (9 per graph)
__device__ int g_c2[NGR];                // attn-done counters (6 per graph)

// ---------------------------------------------------------------------------
// cp.async helpers
// ---------------------------------------------------------------------------
__device__ __forceinline__ void cp16(unsigned int dst, const void* src) {
    asm volatile("cp.async.cg.shared.global [%0], [%1], 16;\n" :: "r"(dst), "l"(src));
}
__device__ __forceinline__ void cp_commit() {
    asm volatile("cp.async.commit_group;\n");
}
template <int N>
__device__ __forceinline__ void cp_wait() {
    asm volatile("cp.async.wait_group %0;\n" :: "n"(N));
}

// ---------------------------------------------------------------------------
// One-shot convert: x and the 4 weight matrices -> fp16.
// Block 0 also resets the dataflow counters.
// ---------------------------------------------------------------------------
__global__ __launch_bounds__(256) void split_kernel(
    const float* __restrict__ x,
    const float* __restrict__ wq, const float* __restrict__ wk,
    const float* __restrict__ wv, const float* __restrict__ wo,
    __half* __restrict__ xh, __half* __restrict__ wh)
{
    const int bid = blockIdx.x;
    if (bid == 0 && threadIdx.x < 2 * NGR) {
        if (threadIdx.x < NGR) g_c1[threadIdx.x] = 0;
        else                   g_c2[threadIdx.x - NGR] = 0;
    }
    const float* src;
    __half* dst;
    int loc;
    if (bid < XN / 1024) {
        loc = (bid * 256 + threadIdx.x) * 4;
        src = x; dst = xh;
    } else {
        int w = ((bid - XN / 1024) * 256 + threadIdx.x) * 4;   // [0, 4*WN)
        int m = w / WN;
        loc = w - m * WN;
        src = (m == 0) ? wq : (m == 1) ? wk : (m == 2) ? wv : wo;
        dst = wh + m * WN;
    }
    float4 v4 = *reinterpret_cast<const float4*>(&src[loc]);
    __half2 hp0(__float2half(v4.x), __float2half(v4.y));
    __half2 hp1(__float2half(v4.z), __float2half(v4.w));
    *reinterpret_cast<uint2*>(&dst[loc]) = make_uint2(
        *reinterpret_cast<unsigned*>(&hp0), *reinterpret_cast<unsigned*>(&hp1));
}

// ---------------------------------------------------------------------------
// GEMM tile, pure fp16, BM=64, BN=128, BK=32/iter, 128 threads = 4 warps
// (each warp 32x64 = 2x4 accumulators). 3-stage cp.async ring.
//   O[br*64:+64, bc*128:+128] = A @ B + bias  (fp32 accumulate + out)
// ---------------------------------------------------------------------------
#define ASTR 40                      // A smem row stride (elems) = 80B
#define BSTR 136                     // B smem row stride (elems) = 272B
#define AH_O 0
#define BH_O 5120                    // 64 rows * 80B
#define STG_BYTES 13824              // + 32 rows * 272B
#define DSM_BYTES (3 * STG_BYTES)    // 41472

__device__ __forceinline__ void gemm_tile(
    unsigned char* dsm,
    const __half* __restrict__ Ah, const __half* __restrict__ Bh,
    const float* __restrict__ bias, float* __restrict__ O,
    int br, int bc, int K, int N)
{
    const unsigned int sbase = (unsigned int)__cvta_generic_to_shared(dsm);
    const int tid  = threadIdx.x;
    const int warp = tid >> 5;
    const int wr   = warp >> 1;        // 0..1: 32-row band
    const int wc   = warp & 1;         // 0..1: 64-col band
    const int niter = K >> 5;          // 12 for K=384

    // A tile 64x32 fp16 (64B/row): 256 16B-segs, 2/thread. r=s>>2, c=s&3.
    const int ar0 = tid >> 2,           ac0 = (tid & 3) * 16;
    const int ar1 = (tid + 128) >> 2,   ac1 = ((tid + 128) & 3) * 16;

    const __half* agh0 = Ah + (long)(br * 64 + ar0) * K + (ac0 >> 1);
    const __half* agh1 = Ah + (long)(br * 64 + ar1) * K + (ac1 >> 1);
    const unsigned int saa0 = ar0 * (ASTR * 2) + ac0;
    const unsigned int saa1 = ar1 * (ASTR * 2) + ac1;

    // B tile 32x128 fp16 (256B/row): 512 segs, 4/thread. r=s>>4, c=s&15.
    int brr[4], bcc[4];
    const __half* bg[4];
    unsigned int sab[4];
    #pragma unroll
    for (int j = 0; j < 4; j++) {
        int s = tid + j * 128;
        brr[j] = s >> 4; bcc[j] = (s & 15) * 16;
        bg[j] = Bh + (long)brr[j] * N + bc * 128 + (bcc[j] >> 1);
        sab[j] = brr[j] * (BSTR * 2) + bcc[j];
    }

    auto load_stage = [&](int stg, int it) {
        const unsigned sb = sbase + stg * STG_BYTES;
        const int ko = it * 32;
        const long bko = (long)it * 32 * N;
        cp16(sb + AH_O + saa0, agh0 + ko);
        cp16(sb + AH_O + saa1, agh1 + ko);
        #pragma unroll
        for (int j = 0; j < 4; j++)
            cp16(sb + BH_O + sab[j], bg[j] + bko);
        cp_commit();
    };

    load_stage(0, 0);
    load_stage(1, 1);

    wmma::fragment<wmma::accumulator, 16, 16, 16, float> acc[2][4];
    #pragma unroll
    for (int i = 0; i < 2; i++)
        #pragma unroll
        for (int j = 0; j < 4; j++)
            wmma::fill_fragment(acc[i][j], 0.0f);

    for (int it = 0; it < niter; it++) {
        const int s = it % 3;
        if (it + 2 < niter) {
            load_stage((it + 2) % 3, it + 2);
            cp_wait<2>();
        } else if (it + 1 < niter) {
            cp_wait<1>();
        } else {
            cp_wait<0>();
        }
        __syncthreads();

        const __half* ash = reinterpret_cast<const __half*>(dsm + s * STG_BYTES + AH_O);
        const __half* bsh = reinterpret_cast<const __half*>(dsm + s * STG_BYTES + BH_O);

        #pragma unroll
        for (int ks = 0; ks < 2; ks++) {
            const int k16 = ks * 16;
            wmma::fragment<wmma::matrix_a, 16, 16, 16, __half, wmma::row_major> ah[2];
            wmma::fragment<wmma::matrix_b, 16, 16, 16, __half, wmma::row_major> bh[4];
            #pragma unroll
            for (int i = 0; i < 2; i++)
                wmma::load_matrix_sync(ah[i], ash + (wr * 32 + i * 16) * ASTR + k16, ASTR);
            #pragma unroll
            for (int j = 0; j < 4; j++)
                wmma::load_matrix_sync(bh[j], bsh + k16 * BSTR + wc * 64 + j * 16, BSTR);
            #pragma unroll
            for (int i = 0; i < 2; i++)
                #pragma unroll
                for (int j = 0; j < 4; j++)
                    wmma::mma_sync(acc[i][j], ah[i], bh[j], acc[i][j]);
        }
        __syncthreads();
    }

    // Epilogue: acc -> aliased fp32 smem (64x128) -> global (+bias), float4
    float (*Cs)[128] = reinterpret_cast<float(*)[128]>(dsm);
    #pragma unroll
    for (int i = 0; i < 2; i++)
        #pragma unroll
        for (int j = 0; j < 4; j++)
            wmma::store_matrix_sync(&Cs[wr * 32 + i * 16][wc * 64 + j * 16],
                                    acc[i][j], 128, wmma::mem_row_major);
    __syncthreads();

    #pragma unroll
    for (int l = 0; l < 16; l++) {
        int idx = tid + l * 128;           // 0..2047 float4 slots
        int r = idx >> 5, c4 = (idx & 31) * 4;
        float4 v = *reinterpret_cast<const float4*>(&Cs[r][c4]);
        const float4 b = *reinterpret_cast<const float4*>(&bias[bc * 128 + c4]);
        v.x += b.x; v.y += b.y; v.z += b.z; v.w += b.w;
        *reinterpret_cast<float4*>(&O[(long)(br * 64 + r) * N + bc * 128 + c4]) = v;
    }
}

// ---------------------------------------------------------------------------
// Mega kernel, 576 CTAs of 128 threads (single wave @4 CTAs/SM):
//   bids [0,288):   QKV GEMM, 9 CTAs per graph (3 mats x 3 col-tiles of 128)
//   bids [288,480): attention, 6 CTAs per graph (4 gh per CTA, 2 rows/thread)
//   bids [480,576): O GEMM, 3 CTAs per graph
// Per-graph atomic counters; bid-ordered dispatch (producers first).
// ---------------------------------------------------------------------------
__global__ __launch_bounds__(128, 4) void mega_kernel(
    const float* __restrict__ pos, const float* __restrict__ freqs,
    const float* __restrict__ bq, const float* __restrict__ bk,
    const float* __restrict__ bv, const float* __restrict__ bo,
    float* __restrict__ out)
{
    extern __shared__ __align__(16) unsigned char dsm[];
    const int bid = blockIdx.x;
    const int tid = threadIdx.x;

    if (bid < 288) {
        // ---- QKV projection: 9 CTAs per graph ----
        const int g     = bid / 9;
        const int rem   = bid % 9;
        const int which = rem / 3;
        const int bc    = rem % 3;
        const __half* Bh = g_wh + (long)which * WN;
        const float* bias = (which == 0) ? bq : (which == 1) ? bk : bv;
        float* O = (which == 0) ? g_q : (which == 1) ? g_k : g_v;
        gemm_tile(dsm, g_xh, Bh, bias, O, g, bc, C, C);
        __threadfence();
        __syncthreads();
        if (tid == 0) atomicAdd(&g_c1[g], 1);

    } else if (bid < 480) {
        // ---- Attention (RoPE fused): 6 CTAs/graph, 4 gh/CTA, 2 rows/thread
        const int a     = bid - 288;
        const int graph = a / 6;
        const int blk   = a % 6;
        const int ghg   = tid >> 5;        // 0..3 gh slice
        const int lane  = tid & 31;
        const int gh    = blk * 4 + ghg;
        const int h     = gh & 1;

        if (tid == 0) {
            while (atomicAdd(&g_c1[graph], 0) < 9) __nanosleep(64);
        }
        __syncthreads();
        __threadfence();

        float (*Ks)[64][16] = reinterpret_cast<float(*)[64][16]>(dsm);
        float (*Vs)[64][16] = reinterpret_cast<float(*)[64][16]>(dsm + 16384);

        float qr[2][16], kr[2][16];
        float p[2][3];
        #pragma unroll
        for (int rr = 0; rr < 2; rr++) {
            const int i    = lane + rr * 32;
            const int node = graph * NPG + i;
            const int off  = node * C + gh * HD;
            const float4* qp = reinterpret_cast<const float4*>(g_q + off);
            const float4* kp = reinterpret_cast<const float4*>(g_k + off);
            const float4* vp = reinterpret_cast<const float4*>(g_v + off);
            float4* vs = reinterpret_cast<float4*>(&Vs[ghg][i][0]);
            #pragma unroll
            for (int t = 0; t < 4; t++) {
                float4 qv = qp[t];
                qr[rr][4*t+0] = qv.x; qr[rr][4*t+1] = qv.y;
                qr[rr][4*t+2] = qv.z; qr[rr][4*t+3] = qv.w;
                float4 kv = kp[t];
                kr[rr][4*t+0] = kv.x; kr[rr][4*t+1] = kv.y;
                kr[rr][4*t+2] = kv.z; kr[rr][4*t+3] = kv.w;
                vs[t] = vp[t];
            }
            p[rr][0] = pos[node * 3 + 0];
            p[rr][1] = pos[node * 3 + 1];
            p[rr][2] = pos[node * 3 + 2];
        }

        #pragma unroll
        for (int rr = 0; rr < 2; rr++) {
            #pragma unroll
            for (int f = 0; f < 8; f++) {
                float th = p[rr][0] * freqs[ 0 + h * 8 + f]
                         + p[rr][1] * freqs[16 + h * 8 + f]
                         + p[rr][2] * freqs[32 + h * 8 + f];
                float s, c;
                __sincosf(th, &s, &c);
                float q1 = qr[rr][2*f], q2 = qr[rr][2*f+1];
                qr[rr][2*f]   = q1 * c - q2 * s;
                qr[rr][2*f+1] = q1 * s + q2 * c;
                float k1 = kr[rr][2*f], k2 = kr[rr][2*f+1];
                kr[rr][2*f]   = k1 * c - k2 * s;
                kr[rr][2*f+1] = k1 * s + k2 * c;
            }
            #pragma unroll
            for (int d = 0; d < 16; d++) qr[rr][d] *= 0.25f;
            #pragma unroll
            for (int d = 0; d < 16; d++) Ks[ghg][lane + rr * 32][d] = kr[rr][d];
        }
        __syncthreads();

        float den[2] = {0.f, 0.f};
        float o0[16] = {}, o1[16] = {};
        #pragma unroll 2
        for (int j = 0; j < 64; j++) {
            float s0 = 0.f, s1 = 0.f;
            #pragma unroll
            for (int d = 0; d < 16; d++) {
                float kv = Ks[ghg][j][d];
                s0 = fmaf(qr[0][d], kv, s0);
                s1 = fmaf(qr[1][d], kv, s1);
            }
            float e0 = __expf(s0), e1 = __expf(s1);
            den[0] += e0; den[1] += e1;
            #pragma unroll
            for (int d = 0; d < 16; d++) {
                float vv = Vs[ghg][j][d];
                o0[d] = fmaf(e0, vv, o0[d]);
                o1[d] = fmaf(e1, vv, o1[d]);
            }
        }

        #pragma unroll
        for (int rr = 0; rr < 2; rr++) {
            const float inv = 1.f / den[rr];
            const float* o = (rr == 0) ? o0 : o1;
            const int node = graph * NPG + lane + rr * 32;
            const int off  = node * C + gh * HD;
            __half hb[16];
            #pragma unroll
            for (int d = 0; d < 16; d++) hb[d] = __float2half(o[d] * inv);
            uint4 uh0, uh1;
            unsigned* uhp0 = &uh0.x; unsigned* uhp1 = &uh1.x;
            #pragma unroll
            for (int t = 0; t < 4; t++) {
                __half2 a2(hb[2*t], hb[2*t+1]);      uhp0[t] = *reinterpret_cast<unsigned*>(&a2);
                __half2 b2(hb[8+2*t], hb[8+2*t+1]);  uhp1[t] = *reinterpret_cast<unsigned*>(&b2);
            }
            uint4* ahp = reinterpret_cast<uint4*>(&g_ah[off]);
            ahp[0] = uh0; ahp[1] = uh1;
        }

        __threadfence();
        __syncthreads();
        if (tid == 0) atomicAdd(&g_c2[graph], 1);

    } else {
        // ---- Output projection: row-tile = graph, 3 CTAs per graph ----
        const int o  = bid - 480;
        const int br = o / 3;
        const int bc = o % 3;

        if (tid == 0) {
            while (atomicAdd(&g_c2[br], 0) < 6) __nanosleep(64);
        }
        __syncthreads();
        __threadfence();

        gemm_tile(dsm, g_ah, g_wh + 3L * WN, bo, out, br, bc, C, C);
    }
}

// ---------------------------------------------------------------------------
extern "C" void kernel_launch(void* const* d_in, const int* in_sizes, int n_in,
                              void* d_out, int out_size)
{
    const float* x     = (const float*)d_in[0];
    const float* pos   = (const float*)d_in[1];
    const float* Wq    = (const float*)d_in[2];
    const float* bq    = (const float*)d_in[3];
    const float* Wk    = (const float*)d_in[4];
    const float* bk    = (const float*)d_in[5];
    const float* Wv    = (const float*)d_in[6];
    const float* bv    = (const float*)d_in[7];
    const float* Wo    = (const float*)d_in[8];
    const float* bo    = (const float*)d_in[9];
    const float* rfreq = (const float*)d_in[10];
    float* out = (float*)d_out;

    __half *xh, *wh;
    cudaGetSymbolAddress((void**)&xh, g_xh);
    cudaGetSymbolAddress((void**)&wh, g_wh);

    cudaFuncSetAttribute(mega_kernel,
                         cudaFuncAttributeMaxDynamicSharedMemorySize, DSM_BYTES);

    // 1) Convert x and weights to fp16 + reset dataflow counters
    int nblk = XN / 1024 + 4 * WN / 1024;     // 1344
    split_kernel<<<nblk, 256>>>(x, Wq, Wk, Wv, Wo, xh, wh);

    // 2) Fused QKV + attention + O-projection, single-wave dataflow
    mega_kernel<<<576, 128, DSM_BYTES>>>(pos, rfreq, bq, bk, bv, bo, out);
}